// round 7
// baseline (speedup 1.0000x reference)
#include <cuda_runtime.h>
#include <math.h>
#include <stdint.h>

// Problem constants
constexpr int Bb  = 2;
constexpr int Nn  = 2048;
constexpr int Dd  = 1024;
constexpr int Hh  = 16;
constexpr int DHh = 64;
constexpr int D3  = 3 * Dd;   // 3072
constexpr int STAGES = 3;

// Scratch (allocation-free rule: __device__ globals)
__device__ float g_qkv[Bb * Nn * D3];     // [B,N,3*H*DH]
__device__ float g_xr[Bb * Nn * Dd];      // x, tf32-rounded + repacked
__device__ float g_wwr[D3 * Dd];          // W_w, rounded + repacked
__device__ float g_owr[Dd * Dd];          // out_w, rounded + repacked
__device__ float g_attnr[Bb * Nn * Dd];   // attn out, rounded + repacked
__device__ float g_kr[Bb * Hh * Nn * DHh];   // K rounded+repacked, [bh][n][64]
__device__ float g_vt[Bb * Hh * DHh * Nn];   // V rounded+transposed, [bh][dh][n]

// ---------------------------------------------------------------------------
// helpers
// ---------------------------------------------------------------------------
__device__ __forceinline__ uint32_t f2tf32(float x) {
    uint32_t r;
    asm("cvt.rna.tf32.f32 %0, %1;" : "=r"(r) : "f"(x));
    return r;
}
__device__ __forceinline__ float f2tf32f(float x) {
    return __uint_as_float(f2tf32(x));
}

__device__ __forceinline__ void mma_tf32(
    float& c0, float& c1, float& c2, float& c3,
    uint32_t a0, uint32_t a1, uint32_t a2, uint32_t a3,
    uint32_t b0, uint32_t b1)
{
    asm volatile(
        "mma.sync.aligned.m16n8k8.row.col.f32.tf32.tf32.f32 "
        "{%0,%1,%2,%3}, {%4,%5,%6,%7}, {%8,%9}, {%0,%1,%2,%3};\n"
        : "+f"(c0), "+f"(c1), "+f"(c2), "+f"(c3)
        : "r"(a0), "r"(a1), "r"(a2), "r"(a3), "r"(b0), "r"(b1));
}

__device__ __forceinline__ void mma_tf32a(
    float* c, const uint32_t* a, uint32_t b0, uint32_t b1)
{
    mma_tf32(c[0], c[1], c[2], c[3], a[0], a[1], a[2], a[3], b0, b1);
}

__device__ __forceinline__ void cp_async16(uint32_t smem, const void* g) {
    asm volatile("cp.async.cg.shared.global [%0], [%1], 16;\n"
                 :: "r"(smem), "l"(g));
}

// ---------------------------------------------------------------------------
// Round to tf32 (rna) + repack: within each 16-float group,
// out[4*(j%4)+j/4] = in[j].
// ---------------------------------------------------------------------------
__global__ void repack_tf32(const float* __restrict__ in,
                            float* __restrict__ out, int ngroups)
{
    int g = blockIdx.x * blockDim.x + threadIdx.x;
    if (g >= ngroups) return;
    const float4* ip = (const float4*)in + (size_t)g * 4;
    float4 v0 = ip[0], v1 = ip[1], v2 = ip[2], v3 = ip[3];
    float4* op = (float4*)out + (size_t)g * 4;
    op[0] = make_float4(f2tf32f(v0.x), f2tf32f(v1.x), f2tf32f(v2.x), f2tf32f(v3.x));
    op[1] = make_float4(f2tf32f(v0.y), f2tf32f(v1.y), f2tf32f(v2.y), f2tf32f(v3.y));
    op[2] = make_float4(f2tf32f(v0.z), f2tf32f(v1.z), f2tf32f(v2.z), f2tf32f(v3.z));
    op[3] = make_float4(f2tf32f(v0.w), f2tf32f(v1.w), f2tf32f(v2.w), f2tf32f(v3.w));
}

// ---------------------------------------------------------------------------
// prep_kv: round K to tf32 + repack along dh -> g_kr[bh][n][64];
//          round V + transpose -> g_vt[bh][dh][n] with repack along n.
// One thread per (bh, c16, n): 16 K floats + 16 V floats.
// ---------------------------------------------------------------------------
__global__ void prep_kv(const float* __restrict__ qkv,
                        float* __restrict__ kr, float* __restrict__ vt)
{
    int idx = blockIdx.x * blockDim.x + threadIdx.x;
    int n   = idx & (Nn - 1);
    int c16 = (idx >> 11) & 3;
    int bh  = idx >> 13;                  // 0..31
    int b   = bh >> 4, h = bh & 15;

    const float* src = qkv + ((size_t)(b * Nn + n)) * D3 + h * DHh + c16 * 16;

    // K: read 16, round, 4x4-repack, write contiguous
    {
        const float4* kp = (const float4*)(src + Dd);
        float4 v0 = kp[0], v1 = kp[1], v2 = kp[2], v3 = kp[3];
        float4* kd = (float4*)(kr + (((size_t)bh * Nn + n)) * 64 + c16 * 16);
        kd[0] = make_float4(f2tf32f(v0.x), f2tf32f(v1.x), f2tf32f(v2.x), f2tf32f(v3.x));
        kd[1] = make_float4(f2tf32f(v0.y), f2tf32f(v1.y), f2tf32f(v2.y), f2tf32f(v3.y));
        kd[2] = make_float4(f2tf32f(v0.z), f2tf32f(v1.z), f2tf32f(v2.z), f2tf32f(v3.z));
        kd[3] = make_float4(f2tf32f(v0.w), f2tf32f(v1.w), f2tf32f(v2.w), f2tf32f(v3.w));
    }

    // V: transpose; dest column = n repacked within its 16-group
    {
        const float* vsrc = src + 2 * Dd;
        int npm = (n & ~15) + 4 * (n & 3) + ((n >> 2) & 3);
        float* vd = vt + (((size_t)bh * 64 + c16 * 16)) * Nn + npm;
        #pragma unroll
        for (int i = 0; i < 16; i++)
            vd[(size_t)i * Nn] = f2tf32f(vsrc[i]);
    }
}

// ---------------------------------------------------------------------------
// Tensor-core GEMM v4: C[M,N] = A[M,K] @ B[N,K]^T + bias[N]
// (unchanged from R6; operands pre-rounded + pre-repacked)
// ---------------------------------------------------------------------------
__global__ __launch_bounds__(256, 2) void tgemm_v4(
    const float* __restrict__ A, const float* __restrict__ B,
    const float* __restrict__ bias, float* __restrict__ C,
    int M, int N, int K)
{
    __shared__ float4 As[STAGES][512];
    __shared__ float4 Bs[STAGES][512];

    const int tid  = threadIdx.x;
    const int lane = tid & 31;
    const int w    = tid >> 5;
    const int qr   = lane >> 2;
    const int qc   = lane & 3;
    const int wm   = w & 3;
    const int wn   = w >> 2;
    const int m0   = blockIdx.y * 128;
    const int n0   = blockIdx.x * 128;

    const int r0 = tid >> 2;
    const int g0 = tid & 3;
    const float* Ag0 = A + (size_t)(m0 + r0) * K + g0 * 4;
    const float* Ag1 = A + (size_t)(m0 + 64 + r0) * K + g0 * 4;
    const float* Bg0 = B + (size_t)(n0 + r0) * K + g0 * 4;
    const float* Bg1 = B + (size_t)(n0 + 64 + r0) * K + g0 * 4;

    uint32_t sA[STAGES], sB[STAGES];
    #pragma unroll
    for (int s = 0; s < STAGES; s++) {
        sA[s] = (uint32_t)__cvta_generic_to_shared(&As[s][tid]);
        sB[s] = (uint32_t)__cvta_generic_to_shared(&Bs[s][tid]);
    }

    float acc[2][8][4];
    #pragma unroll
    for (int f = 0; f < 2; f++)
        #pragma unroll
        for (int nt = 0; nt < 8; nt++)
            #pragma unroll
            for (int i = 0; i < 4; i++) acc[f][nt][i] = 0.f;

    const int nch = K / 16;

    #pragma unroll
    for (int s = 0; s < STAGES - 1; s++) {
        cp_async16(sA[s],            Ag0 + s * 16);
        cp_async16(sA[s] + 256 * 16, Ag1 + s * 16);
        cp_async16(sB[s],            Bg0 + s * 16);
        cp_async16(sB[s] + 256 * 16, Bg1 + s * 16);
        asm volatile("cp.async.commit_group;\n");
    }

    for (int ch = 0; ch < nch; ch++) {
        asm volatile("cp.async.wait_group %0;\n" :: "n"(STAGES - 2));
        __syncthreads();

        const int buf = ch % STAGES;
        const float4* Ap = As[buf];
        const float4* Bp = Bs[buf];

        float4 A00 = Ap[(wm * 32 + qr) * 4 + qc];
        float4 A01 = Ap[(wm * 32 + 8 + qr) * 4 + qc];
        float4 A10 = Ap[(wm * 32 + 16 + qr) * 4 + qc];
        float4 A11 = Ap[(wm * 32 + 24 + qr) * 4 + qc];

        #pragma unroll
        for (int nt = 0; nt < 8; nt++) {
            float4 bv = Bp[(wn * 64 + nt * 8 + qr) * 4 + qc];
            mma_tf32(acc[0][nt][0], acc[0][nt][1], acc[0][nt][2], acc[0][nt][3],
                     __float_as_uint(A00.x), __float_as_uint(A01.x),
                     __float_as_uint(A00.y), __float_as_uint(A01.y),
                     __float_as_uint(bv.x),  __float_as_uint(bv.y));
            mma_tf32(acc[1][nt][0], acc[1][nt][1], acc[1][nt][2], acc[1][nt][3],
                     __float_as_uint(A10.x), __float_as_uint(A11.x),
                     __float_as_uint(A10.y), __float_as_uint(A11.y),
                     __float_as_uint(bv.x),  __float_as_uint(bv.y));
            mma_tf32(acc[0][nt][0], acc[0][nt][1], acc[0][nt][2], acc[0][nt][3],
                     __float_as_uint(A00.z), __float_as_uint(A01.z),
                     __float_as_uint(A00.w), __float_as_uint(A01.w),
                     __float_as_uint(bv.z),  __float_as_uint(bv.w));
            mma_tf32(acc[1][nt][0], acc[1][nt][1], acc[1][nt][2], acc[1][nt][3],
                     __float_as_uint(A10.z), __float_as_uint(A11.z),
                     __float_as_uint(A10.w), __float_as_uint(A11.w),
                     __float_as_uint(bv.z),  __float_as_uint(bv.w));
        }

        const int nc = ch + STAGES - 1;
        if (nc < nch) {
            const int s = nc % STAGES;
            cp_async16(sA[s],            Ag0 + nc * 16);
            cp_async16(sA[s] + 256 * 16, Ag1 + nc * 16);
            cp_async16(sB[s],            Bg0 + nc * 16);
            cp_async16(sB[s] + 256 * 16, Bg1 + nc * 16);
        }
        asm volatile("cp.async.commit_group;\n");
    }

    #pragma unroll
    for (int f = 0; f < 2; f++) {
        const int r = m0 + wm * 32 + f * 16 + qr;
        float* Crow0 = C + (size_t)r * N + n0 + wn * 64;
        float* Crow1 = C + (size_t)(r + 8) * N + n0 + wn * 64;
        #pragma unroll
        for (int nt = 0; nt < 8; nt++) {
            const int c = nt * 8 + qc * 2;
            float2 bv = *(const float2*)&bias[n0 + wn * 64 + c];
            *(float2*)&Crow0[c] = make_float2(acc[f][nt][0] + bv.x,
                                              acc[f][nt][1] + bv.y);
            *(float2*)&Crow1[c] = make_float2(acc[f][nt][2] + bv.x,
                                              acc[f][nt][3] + bv.y);
        }
    }
}

// ---------------------------------------------------------------------------
// Flash attention v2: pre-packed K / V^T operands, cp.async 2-stage pipeline,
// all fragment loads LDS.128 (row stride 20 float4s => conflict-free).
// Epilogue writes rounded + repacked attnr (GEMM2's A operand) directly.
// Dynamic smem: 2 stages x (K tile + V tile) x 1280 float4 = 80 KB.
// ---------------------------------------------------------------------------
__global__ __launch_bounds__(256) void flash_attn_v2(
    const float* __restrict__ qkv, const float* __restrict__ kr,
    const float* __restrict__ vt, float* __restrict__ attnr)
{
    extern __shared__ float4 dsm[];
    constexpr int TILE4 = 64 * 20;   // 1280 float4 per tile

    const int tid  = threadIdx.x;
    const int lane = tid & 31;
    const int w    = tid >> 5;
    const int qr   = lane >> 2;
    const int qc   = lane & 3;
    const int h    = blockIdx.y;
    const int b    = blockIdx.z;
    const int q0   = blockIdx.x * 128;
    const int row0 = w * 16;
    const int bh   = b * Hh + h;

    // ---- Q into A-fragments (scaled), once ----
    uint32_t Qa[8][4];
    {
        const float* qb    = qkv + ((size_t)(b * Nn + q0)) * D3 + h * DHh;
        const float* qrow0 = qb + (size_t)(row0 + qr) * D3;
        const float* qrow1 = qb + (size_t)(row0 + qr + 8) * D3;
        #pragma unroll
        for (int k = 0; k < 8; k++) {
            Qa[k][0] = f2tf32(qrow0[k * 8 + qc]     * 0.125f);
            Qa[k][1] = f2tf32(qrow1[k * 8 + qc]     * 0.125f);
            Qa[k][2] = f2tf32(qrow0[k * 8 + qc + 4] * 0.125f);
            Qa[k][3] = f2tf32(qrow1[k * 8 + qc + 4] * 0.125f);
        }
    }

    float O[8][4];
    #pragma unroll
    for (int nt = 0; nt < 8; nt++)
        #pragma unroll
        for (int i = 0; i < 4; i++) O[nt][i] = 0.f;
    float mA = -1e30f, mB = -1e30f, lA = 0.f, lB = 0.f;

    // staging mapping: thread -> (row sr, 16-float segment)
    const int sr = tid >> 2;
    const int sc = (tid & 3) * 16;
    const float* gk = kr + ((size_t)bh * Nn + sr) * 64 + sc;     // +t*4096
    const float* gv = vt + ((size_t)bh * 64 + sr) * Nn + sc;     // +t*64

    uint32_t kdst[2], vdst[2];
    #pragma unroll
    for (int s = 0; s < 2; s++) {
        kdst[s] = (uint32_t)__cvta_generic_to_shared(
            &dsm[s * 2 * TILE4 + sr * 20 + (tid & 3) * 4]);
        vdst[s] = (uint32_t)__cvta_generic_to_shared(
            &dsm[s * 2 * TILE4 + TILE4 + sr * 20 + (tid & 3) * 4]);
    }

    auto stage_tile = [&](int t, int s) {
        const float* ks = gk + (size_t)t * 4096;
        const float* vs = gv + (size_t)t * 64;
        #pragma unroll
        for (int j = 0; j < 4; j++) {
            cp_async16(kdst[s] + 16 * j, ks + 4 * j);
            cp_async16(vdst[s] + 16 * j, vs + 4 * j);
        }
        asm volatile("cp.async.commit_group;\n");
    };

    stage_tile(0, 0);
    stage_tile(1, 1);

    const int NT = Nn / 64;
    for (int t = 0; t < NT; t++) {
        asm volatile("cp.async.wait_group %0;\n" :: "n"(1));
        __syncthreads();

        const float4* Kp = dsm + (t & 1) * 2 * TILE4;
        const float4* Vp = Kp + TILE4;

        // ---- S = Q @ K^T ----
        float S[8][4];
        #pragma unroll
        for (int nt = 0; nt < 8; nt++) {
            const float4* kp = Kp + (nt * 8 + qr) * 20 + qc;
            float4 k0 = kp[0], k1 = kp[4], k2 = kp[8], k3 = kp[12];
            float c0 = 0.f, c1 = 0.f, c2 = 0.f, c3 = 0.f;
            mma_tf32(c0,c1,c2,c3, Qa[0][0],Qa[0][1],Qa[0][2],Qa[0][3],
                     __float_as_uint(k0.x), __float_as_uint(k0.y));
            mma_tf32(c0,c1,c2,c3, Qa[1][0],Qa[1][1],Qa[1][2],Qa[1][3],
                     __float_as_uint(k0.z), __float_as_uint(k0.w));
            mma_tf32(c0,c1,c2,c3, Qa[2][0],Qa[2][1],Qa[2][2],Qa[2][3],
                     __float_as_uint(k1.x), __float_as_uint(k1.y));
            mma_tf32(c0,c1,c2,c3, Qa[3][0],Qa[3][1],Qa[3][2],Qa[3][3],
                     __float_as_uint(k1.z), __float_as_uint(k1.w));
            mma_tf32(c0,c1,c2,c3, Qa[4][0],Qa[4][1],Qa[4][2],Qa[4][3],
                     __float_as_uint(k2.x), __float_as_uint(k2.y));
            mma_tf32(c0,c1,c2,c3, Qa[5][0],Qa[5][1],Qa[5][2],Qa[5][3],
                     __float_as_uint(k2.z), __float_as_uint(k2.w));
            mma_tf32(c0,c1,c2,c3, Qa[6][0],Qa[6][1],Qa[6][2],Qa[6][3],
                     __float_as_uint(k3.x), __float_as_uint(k3.y));
            mma_tf32(c0,c1,c2,c3, Qa[7][0],Qa[7][1],Qa[7][2],Qa[7][3],
                     __float_as_uint(k3.z), __float_as_uint(k3.w));
            S[nt][0] = c0; S[nt][1] = c1; S[nt][2] = c2; S[nt][3] = c3;
        }

        // ---- online softmax ----
        float cmA = -1e30f, cmB = -1e30f;
        #pragma unroll
        for (int nt = 0; nt < 8; nt++) {
            cmA = fmaxf(cmA, fmaxf(S[nt][0], S[nt][1]));
            cmB = fmaxf(cmB, fmaxf(S[nt][2], S[nt][3]));
        }
        cmA = fmaxf(cmA, __shfl_xor_sync(0xffffffffu, cmA, 1));
        cmA = fmaxf(cmA, __shfl_xor_sync(0xffffffffu, cmA, 2));
        cmB = fmaxf(cmB, __shfl_xor_sync(0xffffffffu, cmB, 1));
        cmB = fmaxf(cmB, __shfl_xor_sync(0xffffffffu, cmB, 2));

        const float mnA = fmaxf(mA, cmA), mnB = fmaxf(mB, cmB);
        const float corrA = __expf(mA - mnA), corrB = __expf(mB - mnB);
        #pragma unroll
        for (int nt = 0; nt < 8; nt++) {
            O[nt][0] *= corrA; O[nt][1] *= corrA;
            O[nt][2] *= corrB; O[nt][3] *= corrB;
        }

        // ---- P = exp(S-mn), transpose C->A layout via quad shuffles ----
        uint32_t pA[8][4];
        float psA = 0.f, psB = 0.f;
        {
            const int quadbase = lane & ~3;
            const int s0l = quadbase | (qc >> 1);
            const int s1l = s0l + 2;
            const bool odd = qc & 1;
            #pragma unroll
            for (int ks = 0; ks < 8; ks++) {
                float p0 = __expf(S[ks][0] - mnA);
                float p1 = __expf(S[ks][1] - mnA);
                float p2 = __expf(S[ks][2] - mnB);
                float p3 = __expf(S[ks][3] - mnB);
                psA += p0 + p1;
                psB += p2 + p3;

                float g00 = __shfl_sync(0xffffffffu, p0, s0l);
                float g01 = __shfl_sync(0xffffffffu, p1, s0l);
                float g20 = __shfl_sync(0xffffffffu, p2, s0l);
                float g21 = __shfl_sync(0xffffffffu, p3, s0l);
                float h00 = __shfl_sync(0xffffffffu, p0, s1l);
                float h01 = __shfl_sync(0xffffffffu, p1, s1l);
                float h20 = __shfl_sync(0xffffffffu, p2, s1l);
                float h21 = __shfl_sync(0xffffffffu, p3, s1l);

                pA[ks][0] = f2tf32(odd ? g01 : g00);
                pA[ks][1] = f2tf32(odd ? g21 : g20);
                pA[ks][2] = f2tf32(odd ? h01 : h00);
                pA[ks][3] = f2tf32(odd ? h21 : h20);
            }
        }
        psA += __shfl_xor_sync(0xffffffffu, psA, 1);
        psA += __shfl_xor_sync(0xffffffffu, psA, 2);
        psB += __shfl_xor_sync(0xffffffffu, psB, 1);
        psB += __shfl_xor_sync(0xffffffffu, psB, 2);
        lA = lA * corrA + psA; mA = mnA;
        lB = lB * corrB + psB; mB = mnB;

        // ---- O += P @ V (nt-outer; V fragments are LDS.128) ----
        #pragma unroll
        for (int nt = 0; nt < 8; nt++) {
            const float4* vp = Vp + (nt * 8 + qr) * 20 + qc;
            float4 v0 = vp[0], v1 = vp[4], v2 = vp[8], v3 = vp[12];
            mma_tf32a(O[nt], pA[0], __float_as_uint(v0.x), __float_as_uint(v0.y));
            mma_tf32a(O[nt], pA[1], __float_as_uint(v0.z), __float_as_uint(v0.w));
            mma_tf32a(O[nt], pA[2], __float_as_uint(v1.x), __float_as_uint(v1.y));
            mma_tf32a(O[nt], pA[3], __float_as_uint(v1.z), __float_as_uint(v1.w));
            mma_tf32a(O[nt], pA[4], __float_as_uint(v2.x), __float_as_uint(v2.y));
            mma_tf32a(O[nt], pA[5], __float_as_uint(v2.z), __float_as_uint(v2.w));
            mma_tf32a(O[nt], pA[6], __float_as_uint(v3.x), __float_as_uint(v3.y));
            mma_tf32a(O[nt], pA[7], __float_as_uint(v3.z), __float_as_uint(v3.w));
        }

        __syncthreads();             // all warps done with stage t&1
        if (t + 2 < NT) stage_tile(t + 2, t & 1);
        else asm volatile("cp.async.commit_group;\n");
    }

    // ---- epilogue: write rounded + repacked attnr directly ----
    const float invA = 1.f / lA, invB = 1.f / lB;
    float* r0p = attnr + ((size_t)(b * Nn + q0 + row0 + qr)) * Dd;
    float* r1p = r0p + (size_t)8 * Dd;
    #pragma unroll
    for (int nt = 0; nt < 8; nt++) {
        #pragma unroll
        for (int e = 0; e < 2; e++) {
            const int j  = h * 64 + nt * 8 + qc * 2 + e;
            const int pj = (j & ~15) + 4 * (j & 3) + ((j >> 2) & 3);
            r0p[pj] = f2tf32f(O[nt][e]     * invA);
            r1p[pj] = f2tf32f(O[nt][2 + e] * invB);
        }
    }
}

// ---------------------------------------------------------------------------
// Host launcher
// ---------------------------------------------------------------------------
extern "C" void kernel_launch(void* const* d_in, const int* in_sizes, int n_in,
                              void* d_out, int out_size)
{
    const float* x     = (const float*)d_in[0];
    const float* W_w   = (const float*)d_in[1];
    const float* W_b   = (const float*)d_in[2];
    const float* out_w = (const float*)d_in[3];
    const float* out_b = (const float*)d_in[4];

    float *qkv, *xr, *wwr, *owr, *attnr, *kr, *vt;
    cudaGetSymbolAddress((void**)&qkv,   g_qkv);
    cudaGetSymbolAddress((void**)&xr,    g_xr);
    cudaGetSymbolAddress((void**)&wwr,   g_wwr);
    cudaGetSymbolAddress((void**)&owr,   g_owr);
    cudaGetSymbolAddress((void**)&attnr, g_attnr);
    cudaGetSymbolAddress((void**)&kr,    g_kr);
    cudaGetSymbolAddress((void**)&vt,    g_vt);

    const int M = Bb * Nn;   // 4096
    const int ATTN_SMEM = 2 * 2 * 64 * 20 * 16;   // 81920 B

    cudaFuncSetAttribute(flash_attn_v2,
                         cudaFuncAttributeMaxDynamicSharedMemorySize,
                         ATTN_SMEM);

    // pre-pass: round + repack GEMM operands
    {
        int ng;
        ng = M * Dd / 16;
        repack_tf32<<<(ng + 255) / 256, 256>>>(x, xr, ng);
        ng = D3 * Dd / 16;
        repack_tf32<<<(ng + 255) / 256, 256>>>(W_w, wwr, ng);
        ng = Dd * Dd / 16;
        repack_tf32<<<(ng + 255) / 256, 256>>>(out_w, owr, ng);
    }

    // qkv = x @ W_w^T + W_b
    tgemm_v4<<<dim3(D3 / 128, M / 128), 256>>>(xr, wwr, W_b, qkv, M, D3, Dd);

    // prep K/V operand layouts for attention
    prep_kv<<<(Bb * Hh * 4 * Nn) / 256, 256>>>(qkv, kr, vt);

    // attention -> attnr (rounded + repacked)
    flash_attn_v2<<<dim3(Nn / 128, Hh, Bb), 256, ATTN_SMEM>>>(qkv, kr, vt, attnr);

    // out = attn @ out_w^T + out_b
    tgemm_v4<<<dim3(Dd / 128, M / 128), 256>>>(attnr, owr, out_b,
                                               (float*)d_out, M, Dd, Dd);
}

// round 8
// speedup vs baseline: 1.0474x; 1.0474x over previous
#include <cuda_runtime.h>
#include <math.h>
#include <stdint.h>

// Problem constants
constexpr int Bb  = 2;
constexpr int Nn  = 2048;
constexpr int Dd  = 1024;
constexpr int Hh  = 16;
constexpr int DHh = 64;
constexpr int D3  = 3 * Dd;   // 3072

// Scratch (allocation-free rule: __device__ globals)
__device__ float g_qkv[Bb * Nn * D3];
__device__ float g_xr[Bb * Nn * Dd];
__device__ float g_wwr[D3 * Dd];
__device__ float g_owr[Dd * Dd];
__device__ float g_attnr[Bb * Nn * Dd];
__device__ float g_kr[Bb * Hh * Nn * DHh];
__device__ float g_vt[Bb * Hh * DHh * Nn];

// ---------------------------------------------------------------------------
// helpers
// ---------------------------------------------------------------------------
__device__ __forceinline__ uint32_t f2tf32(float x) {
    uint32_t r;
    asm("cvt.rna.tf32.f32 %0, %1;" : "=r"(r) : "f"(x));
    return r;
}
__device__ __forceinline__ float f2tf32f(float x) {
    return __uint_as_float(f2tf32(x));
}

__device__ __forceinline__ void mma_tf32(
    float& c0, float& c1, float& c2, float& c3,
    uint32_t a0, uint32_t a1, uint32_t a2, uint32_t a3,
    uint32_t b0, uint32_t b1)
{
    asm volatile(
        "mma.sync.aligned.m16n8k8.row.col.f32.tf32.tf32.f32 "
        "{%0,%1,%2,%3}, {%4,%5,%6,%7}, {%8,%9}, {%0,%1,%2,%3};\n"
        : "+f"(c0), "+f"(c1), "+f"(c2), "+f"(c3)
        : "r"(a0), "r"(a1), "r"(a2), "r"(a3), "r"(b0), "r"(b1));
}

__device__ __forceinline__ void mma_tf32a(
    float* c, const uint32_t* a, uint32_t b0, uint32_t b1)
{
    mma_tf32(c[0], c[1], c[2], c[3], a[0], a[1], a[2], a[3], b0, b1);
}

__device__ __forceinline__ void cp_async16(uint32_t smem, const void* g) {
    asm volatile("cp.async.cg.shared.global [%0], [%1], 16;\n"
                 :: "r"(smem), "l"(g));
}

// ---------------------------------------------------------------------------
// Round to tf32 + 4x4 repack within 16-float groups.
// ---------------------------------------------------------------------------
__global__ void repack_tf32(const float* __restrict__ in,
                            float* __restrict__ out, int ngroups)
{
    int g = blockIdx.x * blockDim.x + threadIdx.x;
    if (g >= ngroups) return;
    const float4* ip = (const float4*)in + (size_t)g * 4;
    float4 v0 = ip[0], v1 = ip[1], v2 = ip[2], v3 = ip[3];
    float4* op = (float4*)out + (size_t)g * 4;
    op[0] = make_float4(f2tf32f(v0.x), f2tf32f(v1.x), f2tf32f(v2.x), f2tf32f(v3.x));
    op[1] = make_float4(f2tf32f(v0.y), f2tf32f(v1.y), f2tf32f(v2.y), f2tf32f(v3.y));
    op[2] = make_float4(f2tf32f(v0.z), f2tf32f(v1.z), f2tf32f(v2.z), f2tf32f(v3.z));
    op[3] = make_float4(f2tf32f(v0.w), f2tf32f(v1.w), f2tf32f(v2.w), f2tf32f(v3.w));
}

// ---------------------------------------------------------------------------
// prep_kv: K -> g_kr[bh][n][64] (rounded, repacked along dh);
//          V -> g_vt[bh][dh][n] (rounded, transposed, repacked along n).
// ---------------------------------------------------------------------------
__global__ void prep_kv(const float* __restrict__ qkv,
                        float* __restrict__ kr, float* __restrict__ vt)
{
    int idx = blockIdx.x * blockDim.x + threadIdx.x;
    int n   = idx & (Nn - 1);
    int c16 = (idx >> 11) & 3;
    int bh  = idx >> 13;
    int b   = bh >> 4, h = bh & 15;

    const float* src = qkv + ((size_t)(b * Nn + n)) * D3 + h * DHh + c16 * 16;

    {
        const float4* kp = (const float4*)(src + Dd);
        float4 v0 = kp[0], v1 = kp[1], v2 = kp[2], v3 = kp[3];
        float4* kd = (float4*)(kr + (((size_t)bh * Nn + n)) * 64 + c16 * 16);
        kd[0] = make_float4(f2tf32f(v0.x), f2tf32f(v1.x), f2tf32f(v2.x), f2tf32f(v3.x));
        kd[1] = make_float4(f2tf32f(v0.y), f2tf32f(v1.y), f2tf32f(v2.y), f2tf32f(v3.y));
        kd[2] = make_float4(f2tf32f(v0.z), f2tf32f(v1.z), f2tf32f(v2.z), f2tf32f(v3.z));
        kd[3] = make_float4(f2tf32f(v0.w), f2tf32f(v1.w), f2tf32f(v2.w), f2tf32f(v3.w));
    }

    {
        const float* vsrc = src + 2 * Dd;
        int npm = (n & ~15) + 4 * (n & 3) + ((n >> 2) & 3);
        float* vd = vt + (((size_t)bh * 64 + c16 * 16)) * Nn + npm;
        #pragma unroll
        for (int i = 0; i < 16; i++)
            vd[(size_t)i * Nn] = f2tf32f(vsrc[i]);
    }
}

// ---------------------------------------------------------------------------
// Tensor-core GEMM v5: C[M,N] = A[M,K=1024] @ B[N,K=1024]^T + bias[N]
// Operands pre-rounded + pre-repacked. 4-stage cp.async pipeline in 64KB
// dynamic smem; chunk loop unrolled x4 so every stage index / smem address
// is a compile-time constant (kills the IMAD/alu issue tax seen in v4).
// Block 128x128, 8 warps (4M x 2N), warp tile 32x64.
// ---------------------------------------------------------------------------
constexpr int GK   = 1024;       // K dim (both GEMMs)
constexpr int GNCH = GK / 16;    // 64 chunks
constexpr int GST  = 4;          // pipeline stages

__global__ __launch_bounds__(256, 2) void tgemm_v5(
    const float* __restrict__ A, const float* __restrict__ B,
    const float* __restrict__ bias, float* __restrict__ C,
    int M, int N)
{
    extern __shared__ float4 gsm[];
    float4* As = gsm;              // [GST][512]
    float4* Bs = gsm + GST * 512;  // [GST][512]

    const int tid  = threadIdx.x;
    const int lane = tid & 31;
    const int w    = tid >> 5;
    const int qr   = lane >> 2;
    const int qc   = lane & 3;
    const int wm   = w & 3;
    const int wn   = w >> 2;
    const int m0   = blockIdx.y * 128;
    const int n0   = blockIdx.x * 128;

    // loader mapping
    const int r0 = tid >> 2;
    const int g0 = tid & 3;
    const float* Ag0 = A + (size_t)(m0 + r0) * GK + g0 * 4;
    const float* Ag1 = A + (size_t)(m0 + 64 + r0) * GK + g0 * 4;
    const float* Bg0 = B + (size_t)(n0 + r0) * GK + g0 * 4;
    const float* Bg1 = B + (size_t)(n0 + 64 + r0) * GK + g0 * 4;

    uint32_t sA[GST], sB[GST];
    #pragma unroll
    for (int s = 0; s < GST; s++) {
        sA[s] = (uint32_t)__cvta_generic_to_shared(&As[s * 512 + tid]);
        sB[s] = (uint32_t)__cvta_generic_to_shared(&Bs[s * 512 + tid]);
    }

    // loop-invariant fragment pointers (one per stage)
    const float4* ApS[GST];
    const float4* BpS[GST];
    #pragma unroll
    for (int s = 0; s < GST; s++) {
        ApS[s] = As + s * 512 + (wm * 32 + qr) * 4 + qc;
        BpS[s] = Bs + s * 512 + (wn * 64 + qr) * 4 + qc;
    }

    float acc[2][8][4];
    #pragma unroll
    for (int f = 0; f < 2; f++)
        #pragma unroll
        for (int nt = 0; nt < 8; nt++)
            #pragma unroll
            for (int i = 0; i < 4; i++) acc[f][nt][i] = 0.f;

    // prefetch chunks 0..2
    #pragma unroll
    for (int s = 0; s < GST - 1; s++) {
        cp_async16(sA[s],            Ag0 + s * 16);
        cp_async16(sA[s] + 256 * 16, Ag1 + s * 16);
        cp_async16(sB[s],            Bg0 + s * 16);
        cp_async16(sB[s] + 256 * 16, Bg1 + s * 16);
        asm volatile("cp.async.commit_group;\n");
    }

    // running source pointers for chunk issue (chunk 3 first)
    const float* a0p = Ag0 + (GST - 1) * 16;
    const float* a1p = Ag1 + (GST - 1) * 16;
    const float* b0p = Bg0 + (GST - 1) * 16;
    const float* b1p = Bg1 + (GST - 1) * 16;

    #pragma unroll 1
    for (int ch = 0; ch < GNCH; ch += GST) {
        #pragma unroll
        for (int s = 0; s < GST; s++) {
            asm volatile("cp.async.wait_group %0;\n" :: "n"(GST - 2));
            __syncthreads();

            const float4* Ap = ApS[s];
            const float4* Bp = BpS[s];
            float4 A00 = Ap[0];
            float4 A01 = Ap[32];
            float4 A10 = Ap[64];
            float4 A11 = Ap[96];

            #pragma unroll
            for (int nt = 0; nt < 8; nt++) {
                float4 bv = Bp[nt * 32];
                mma_tf32(acc[0][nt][0], acc[0][nt][1], acc[0][nt][2], acc[0][nt][3],
                         __float_as_uint(A00.x), __float_as_uint(A01.x),
                         __float_as_uint(A00.y), __float_as_uint(A01.y),
                         __float_as_uint(bv.x),  __float_as_uint(bv.y));
                mma_tf32(acc[1][nt][0], acc[1][nt][1], acc[1][nt][2], acc[1][nt][3],
                         __float_as_uint(A10.x), __float_as_uint(A11.x),
                         __float_as_uint(A10.y), __float_as_uint(A11.y),
                         __float_as_uint(bv.x),  __float_as_uint(bv.y));
                mma_tf32(acc[0][nt][0], acc[0][nt][1], acc[0][nt][2], acc[0][nt][3],
                         __float_as_uint(A00.z), __float_as_uint(A01.z),
                         __float_as_uint(A00.w), __float_as_uint(A01.w),
                         __float_as_uint(bv.z),  __float_as_uint(bv.w));
                mma_tf32(acc[1][nt][0], acc[1][nt][1], acc[1][nt][2], acc[1][nt][3],
                         __float_as_uint(A10.z), __float_as_uint(A11.z),
                         __float_as_uint(A10.w), __float_as_uint(A11.w),
                         __float_as_uint(bv.z),  __float_as_uint(bv.w));
            }

            // issue chunk ch+s+3 into stage (s+3)%4 (compile-time)
            if (ch + s + GST - 1 < GNCH) {
                constexpr int dummy = 0; (void)dummy;
                const int sd = (s + GST - 1) & (GST - 1);
                cp_async16(sA[sd],            a0p);
                cp_async16(sA[sd] + 256 * 16, a1p);
                cp_async16(sB[sd],            b0p);
                cp_async16(sB[sd] + 256 * 16, b1p);
                a0p += 16; a1p += 16; b0p += 16; b1p += 16;
            }
            asm volatile("cp.async.commit_group;\n");
        }
    }

    // epilogue
    #pragma unroll
    for (int f = 0; f < 2; f++) {
        const int r = m0 + wm * 32 + f * 16 + qr;
        float* Crow0 = C + (size_t)r * N + n0 + wn * 64;
        float* Crow1 = C + (size_t)(r + 8) * N + n0 + wn * 64;
        #pragma unroll
        for (int nt = 0; nt < 8; nt++) {
            const int c = nt * 8 + qc * 2;
            float2 bv = *(const float2*)&bias[n0 + wn * 64 + c];
            *(float2*)&Crow0[c] = make_float2(acc[f][nt][0] + bv.x,
                                              acc[f][nt][1] + bv.y);
            *(float2*)&Crow1[c] = make_float2(acc[f][nt][2] + bv.x,
                                              acc[f][nt][3] + bv.y);
        }
    }
}

// ---------------------------------------------------------------------------
// Flash attention v2.1: pre-packed K / V^T, cp.async 2-stage pipeline,
// LDS.128 fragments, base-2 softmax (log2e folded into Q scale).
// ---------------------------------------------------------------------------
__global__ __launch_bounds__(256) void flash_attn_v2(
    const float* __restrict__ qkv, const float* __restrict__ kr,
    const float* __restrict__ vt, float* __restrict__ attnr)
{
    extern __shared__ float4 dsm[];
    constexpr int TILE4 = 64 * 20;
    constexpr float QSCALE = 0.125f * 1.44269504088896341f;  // dh^-0.5 * log2e

    const int tid  = threadIdx.x;
    const int lane = tid & 31;
    const int w    = tid >> 5;
    const int qr   = lane >> 2;
    const int qc   = lane & 3;
    const int h    = blockIdx.y;
    const int b    = blockIdx.z;
    const int q0   = blockIdx.x * 128;
    const int row0 = w * 16;
    const int bh   = b * Hh + h;

    uint32_t Qa[8][4];
    {
        const float* qb    = qkv + ((size_t)(b * Nn + q0)) * D3 + h * DHh;
        const float* qrow0 = qb + (size_t)(row0 + qr) * D3;
        const float* qrow1 = qb + (size_t)(row0 + qr + 8) * D3;
        #pragma unroll
        for (int k = 0; k < 8; k++) {
            Qa[k][0] = f2tf32(qrow0[k * 8 + qc]     * QSCALE);
            Qa[k][1] = f2tf32(qrow1[k * 8 + qc]     * QSCALE);
            Qa[k][2] = f2tf32(qrow0[k * 8 + qc + 4] * QSCALE);
            Qa[k][3] = f2tf32(qrow1[k * 8 + qc + 4] * QSCALE);
        }
    }

    float O[8][4];
    #pragma unroll
    for (int nt = 0; nt < 8; nt++)
        #pragma unroll
        for (int i = 0; i < 4; i++) O[nt][i] = 0.f;
    float mA = -1e30f, mB = -1e30f, lA = 0.f, lB = 0.f;

    const int sr = tid >> 2;
    const float* gk = kr + ((size_t)bh * Nn + sr) * 64 + (tid & 3) * 16;
    const float* gv = vt + ((size_t)bh * 64 + sr) * Nn + (tid & 3) * 16;

    uint32_t kdst[2], vdst[2];
    #pragma unroll
    for (int s = 0; s < 2; s++) {
        kdst[s] = (uint32_t)__cvta_generic_to_shared(
            &dsm[s * 2 * TILE4 + sr * 20 + (tid & 3) * 4]);
        vdst[s] = (uint32_t)__cvta_generic_to_shared(
            &dsm[s * 2 * TILE4 + TILE4 + sr * 20 + (tid & 3) * 4]);
    }

    auto stage_tile = [&](int t, int s) {
        const float* ks = gk + (size_t)t * 4096;
        const float* vs = gv + (size_t)t * 64;
        #pragma unroll
        for (int j = 0; j < 4; j++) {
            cp_async16(kdst[s] + 16 * j, ks + 4 * j);
            cp_async16(vdst[s] + 16 * j, vs + 4 * j);
        }
        asm volatile("cp.async.commit_group;\n");
    };

    stage_tile(0, 0);
    stage_tile(1, 1);

    const int NT = Nn / 64;
    for (int t = 0; t < NT; t++) {
        asm volatile("cp.async.wait_group %0;\n" :: "n"(1));
        __syncthreads();

        const float4* Kp = dsm + (t & 1) * 2 * TILE4;
        const float4* Vp = Kp + TILE4;

        float S[8][4];
        #pragma unroll
        for (int nt = 0; nt < 8; nt++) {
            const float4* kp = Kp + (nt * 8 + qr) * 20 + qc;
            float4 k0 = kp[0], k1 = kp[4], k2 = kp[8], k3 = kp[12];
            float c0 = 0.f, c1 = 0.f, c2 = 0.f, c3 = 0.f;
            mma_tf32(c0,c1,c2,c3, Qa[0][0],Qa[0][1],Qa[0][2],Qa[0][3],
                     __float_as_uint(k0.x), __float_as_uint(k0.y));
            mma_tf32(c0,c1,c2,c3, Qa[1][0],Qa[1][1],Qa[1][2],Qa[1][3],
                     __float_as_uint(k0.z), __float_as_uint(k0.w));
            mma_tf32(c0,c1,c2,c3, Qa[2][0],Qa[2][1],Qa[2][2],Qa[2][3],
                     __float_as_uint(k1.x), __float_as_uint(k1.y));
            mma_tf32(c0,c1,c2,c3, Qa[3][0],Qa[3][1],Qa[3][2],Qa[3][3],
                     __float_as_uint(k1.z), __float_as_uint(k1.w));
            mma_tf32(c0,c1,c2,c3, Qa[4][0],Qa[4][1],Qa[4][2],Qa[4][3],
                     __float_as_uint(k2.x), __float_as_uint(k2.y));
            mma_tf32(c0,c1,c2,c3, Qa[5][0],Qa[5][1],Qa[5][2],Qa[5][3],
                     __float_as_uint(k2.z), __float_as_uint(k2.w));
            mma_tf32(c0,c1,c2,c3, Qa[6][0],Qa[6][1],Qa[6][2],Qa[6][3],
                     __float_as_uint(k3.x), __float_as_uint(k3.y));
            mma_tf32(c0,c1,c2,c3, Qa[7][0],Qa[7][1],Qa[7][2],Qa[7][3],
                     __float_as_uint(k3.z), __float_as_uint(k3.w));
            S[nt][0] = c0; S[nt][1] = c1; S[nt][2] = c2; S[nt][3] = c3;
        }

        float cmA = -1e30f, cmB = -1e30f;
        #pragma unroll
        for (int nt = 0; nt < 8; nt++) {
            cmA = fmaxf(cmA, fmaxf(S[nt][0], S[nt][1]));
            cmB = fmaxf(cmB, fmaxf(S[nt][2], S[nt][3]));
        }
        cmA = fmaxf(cmA, __shfl_xor_sync(0xffffffffu, cmA, 1));
        cmA = fmaxf(cmA, __shfl_xor_sync(0xffffffffu, cmA, 2));
        cmB = fmaxf(cmB, __shfl_xor_sync(0xffffffffu, cmB, 1));
        cmB = fmaxf(cmB, __shfl_xor_sync(0xffffffffu, cmB, 2));

        const float mnA = fmaxf(mA, cmA), mnB = fmaxf(mB, cmB);
        const float corrA = exp2f(mA - mnA), corrB = exp2f(mB - mnB);
        #pragma unroll
        for (int nt = 0; nt < 8; nt++) {
            O[nt][0] *= corrA; O[nt][1] *= corrA;
            O[nt][2] *= corrB; O[nt][3] *= corrB;
        }

        uint32_t pA[8][4];
        float psA = 0.f, psB = 0.f;
        {
            const int quadbase = lane & ~3;
            const int s0l = quadbase | (qc >> 1);
            const int s1l = s0l + 2;
            const bool odd = qc & 1;
            #pragma unroll
            for (int ks = 0; ks < 8; ks++) {
                float p0 = exp2f(S[ks][0] - mnA);
                float p1 = exp2f(S[ks][1] - mnA);
                float p2 = exp2f(S[ks][2] - mnB);
                float p3 = exp2f(S[ks][3] - mnB);
                psA += p0 + p1;
                psB += p2 + p3;

                float g00 = __shfl_sync(0xffffffffu, p0, s0l);
                float g01 = __shfl_sync(0xffffffffu, p1, s0l);
                float g20 = __shfl_sync(0xffffffffu, p2, s0l);
                float g21 = __shfl_sync(0xffffffffu, p3, s0l);
                float h00 = __shfl_sync(0xffffffffu, p0, s1l);
                float h01 = __shfl_sync(0xffffffffu, p1, s1l);
                float h20 = __shfl_sync(0xffffffffu, p2, s1l);
                float h21 = __shfl_sync(0xffffffffu, p3, s1l);

                pA[ks][0] = f2tf32(odd ? g01 : g00);
                pA[ks][1] = f2tf32(odd ? g21 : g20);
                pA[ks][2] = f2tf32(odd ? h01 : h00);
                pA[ks][3] = f2tf32(odd ? h21 : h20);
            }
        }
        psA += __shfl_xor_sync(0xffffffffu, psA, 1);
        psA += __shfl_xor_sync(0xffffffffu, psA, 2);
        psB += __shfl_xor_sync(0xffffffffu, psB, 1);
        psB += __shfl_xor_sync(0xffffffffu, psB, 2);
        lA = lA * corrA + psA; mA = mnA;
        lB = lB * corrB + psB; mB = mnB;

        #pragma unroll
        for (int nt = 0; nt < 8; nt++) {
            const float4* vp = Vp + (nt * 8 + qr) * 20 + qc;
            float4 v0 = vp[0], v1 = vp[4], v2 = vp[8], v3 = vp[12];
            mma_tf32a(O[nt], pA[0], __float_as_uint(v0.x), __float_as_uint(v0.y));
            mma_tf32a(O[nt], pA[1], __float_as_uint(v0.z), __float_as_uint(v0.w));
            mma_tf32a(O[nt], pA[2], __float_as_uint(v1.x), __float_as_uint(v1.y));
            mma_tf32a(O[nt], pA[3], __float_as_uint(v1.z), __float_as_uint(v1.w));
            mma_tf32a(O[nt], pA[4], __float_as_uint(v2.x), __float_as_uint(v2.y));
            mma_tf32a(O[nt], pA[5], __float_as_uint(v2.z), __float_as_uint(v2.w));
            mma_tf32a(O[nt], pA[6], __float_as_uint(v3.x), __float_as_uint(v3.y));
            mma_tf32a(O[nt], pA[7], __float_as_uint(v3.z), __float_as_uint(v3.w));
        }

        __syncthreads();
        if (t + 2 < NT) stage_tile(t + 2, t & 1);
        else asm volatile("cp.async.commit_group;\n");
    }

    const float invA = 1.f / lA, invB = 1.f / lB;
    float* r0p = attnr + ((size_t)(b * Nn + q0 + row0 + qr)) * Dd;
    float* r1p = r0p + (size_t)8 * Dd;
    #pragma unroll
    for (int nt = 0; nt < 8; nt++) {
        #pragma unroll
        for (int e = 0; e < 2; e++) {
            const int j  = h * 64 + nt * 8 + qc * 2 + e;
            const int pj = (j & ~15) + 4 * (j & 3) + ((j >> 2) & 3);
            r0p[pj] = f2tf32f(O[nt][e]     * invA);
            r1p[pj] = f2tf32f(O[nt][2 + e] * invB);
        }
    }
}

// ---------------------------------------------------------------------------
// Host launcher
// ---------------------------------------------------------------------------
extern "C" void kernel_launch(void* const* d_in, const int* in_sizes, int n_in,
                              void* d_out, int out_size)
{
    const float* x     = (const float*)d_in[0];
    const float* W_w   = (const float*)d_in[1];
    const float* W_b   = (const float*)d_in[2];
    const float* out_w = (const float*)d_in[3];
    const float* out_b = (const float*)d_in[4];

    float *qkv, *xr, *wwr, *owr, *attnr, *kr, *vt;
    cudaGetSymbolAddress((void**)&qkv,   g_qkv);
    cudaGetSymbolAddress((void**)&xr,    g_xr);
    cudaGetSymbolAddress((void**)&wwr,   g_wwr);
    cudaGetSymbolAddress((void**)&owr,   g_owr);
    cudaGetSymbolAddress((void**)&attnr, g_attnr);
    cudaGetSymbolAddress((void**)&kr,    g_kr);
    cudaGetSymbolAddress((void**)&vt,    g_vt);

    const int M = Bb * Nn;
    const int GEMM_SMEM = GST * 512 * 16 * 2;     // 65536 B
    const int ATTN_SMEM = 2 * 2 * 64 * 20 * 16;   // 81920 B

    cudaFuncSetAttribute(tgemm_v5,
                         cudaFuncAttributeMaxDynamicSharedMemorySize,
                         GEMM_SMEM);
    cudaFuncSetAttribute(flash_attn_v2,
                         cudaFuncAttributeMaxDynamicSharedMemorySize,
                         ATTN_SMEM);

    {
        int ng;
        ng = M * Dd / 16;
        repack_tf32<<<(ng + 255) / 256, 256>>>(x, xr, ng);
        ng = D3 * Dd / 16;
        repack_tf32<<<(ng + 255) / 256, 256>>>(W_w, wwr, ng);
        ng = Dd * Dd / 16;
        repack_tf32<<<(ng + 255) / 256, 256>>>(out_w, owr, ng);
    }

    // qkv = x @ W_w^T + W_b
    tgemm_v5<<<dim3(D3 / 128, M / 128), 256, GEMM_SMEM>>>(xr, wwr, W_b, qkv, M, D3);

    // prep K/V layouts
    prep_kv<<<(Bb * Hh * 4 * Nn) / 256, 256>>>(qkv, kr, vt);

    // attention -> attnr (rounded + repacked)
    flash_attn_v2<<<dim3(Nn / 128, Hh, Bb), 256, ATTN_SMEM>>>(qkv, kr, vt, attnr);

    // out = attn @ out_w^T + out_b
    tgemm_v5<<<dim3(Dd / 128, M / 128), 256, GEMM_SMEM>>>(attnr, owr, out_b,
                                                          (float*)d_out, M, Dd);
}

// round 10
// speedup vs baseline: 1.1007x; 1.0509x over previous
#include <cuda_runtime.h>
#include <math.h>
#include <stdint.h>

// Problem constants
constexpr int Bb  = 2;
constexpr int Nn  = 2048;
constexpr int Dd  = 1024;
constexpr int Hh  = 16;
constexpr int DHh = 64;
constexpr int D3  = 3 * Dd;   // 3072

// Scratch (allocation-free rule: __device__ globals)
__device__ float g_qkv[Bb * Nn * D3];
__device__ float g_xr[Bb * Nn * Dd];      // x tiles (rounded+repacked+swizzled)
__device__ float g_wwr[D3 * Dd];          // W_w tiles
__device__ float g_owr[Dd * Dd];          // out_w tiles
__device__ float g_attnr[Bb * Nn * Dd];   // attn tiles (written by attention)
__device__ float g_kr[Bb * Hh * Nn * DHh];
__device__ float g_vt[Bb * Hh * DHh * Nn];

// ---------------------------------------------------------------------------
// helpers
// ---------------------------------------------------------------------------
__device__ __forceinline__ uint32_t f2tf32(float x) {
    uint32_t r;
    asm("cvt.rna.tf32.f32 %0, %1;" : "=r"(r) : "f"(x));
    return r;
}
__device__ __forceinline__ float f2tf32f(float x) {
    return __uint_as_float(f2tf32(x));
}

__device__ __forceinline__ void mma_tf32(
    float& c0, float& c1, float& c2, float& c3,
    uint32_t a0, uint32_t a1, uint32_t a2, uint32_t a3,
    uint32_t b0, uint32_t b1)
{
    asm volatile(
        "mma.sync.aligned.m16n8k8.row.col.f32.tf32.tf32.f32 "
        "{%0,%1,%2,%3}, {%4,%5,%6,%7}, {%8,%9}, {%0,%1,%2,%3};\n"
        : "+f"(c0), "+f"(c1), "+f"(c2), "+f"(c3)
        : "r"(a0), "r"(a1), "r"(a2), "r"(a3), "r"(b0), "r"(b1));
}
__device__ __forceinline__ void mma_tf32a(
    float* c, const uint32_t* a, uint32_t b0, uint32_t b1)
{
    mma_tf32(c[0], c[1], c[2], c[3], a[0], a[1], a[2], a[3], b0, b1);
}

__device__ __forceinline__ void cp_async16(uint32_t smem, const void* g) {
    asm volatile("cp.async.cg.shared.global [%0], [%1], 16;\n"
                 :: "r"(smem), "l"(g));
}

// mbarrier + bulk-async (validated to compile for sm_100 in R9)
__device__ __forceinline__ void mbar_init(uint32_t mbar, uint32_t cnt) {
    asm volatile("mbarrier.init.shared.b64 [%0], %1;" :: "r"(mbar), "r"(cnt)
                 : "memory");
}
__device__ __forceinline__ void mbar_expect_tx(uint32_t mbar, uint32_t bytes) {
    asm volatile("mbarrier.arrive.expect_tx.shared.b64 _, [%0], %1;"
                 :: "r"(mbar), "r"(bytes) : "memory");
}
__device__ __forceinline__ void mbar_wait(uint32_t mbar, uint32_t parity) {
    asm volatile(
        "{\n\t.reg .pred P;\n\t"
        "W%=:\n\t"
        "mbarrier.try_wait.parity.shared.b64 P, [%0], %1;\n\t"
        "@!P bra W%=;\n\t}"
        :: "r"(mbar), "r"(parity) : "memory");
}
__device__ __forceinline__ void bulk_g2s(uint32_t dst, const void* src,
                                         uint32_t bytes, uint32_t mbar) {
    asm volatile(
        "cp.async.bulk.shared::cta.global.mbarrier::complete_tx::bytes "
        "[%0], [%1], %2, [%3];"
        :: "r"(dst), "l"(src), "r"(bytes), "r"(mbar) : "memory");
}

// ---------------------------------------------------------------------------
// repack_tiles: round to tf32; store as contiguous 16KB chunks
// [rowblock rb][kblock kb] of 128 rows x 32 floats. Within each 16-float
// group the 4x4 repack is applied (float4 #t holds k%4==t), and the float4
// column is xor-swizzled with (row&1)*4 for conflict-free LDS.128.
// One thread per 16-float group.
// ---------------------------------------------------------------------------
__global__ void repack_tiles(const float* __restrict__ in,
                             float* __restrict__ out, int nrows)
{
    int idx = blockIdx.x * blockDim.x + threadIdx.x;
    if (idx >= nrows * 64) return;
    int R   = idx >> 6;          // row (K=1024 -> 64 groups/row)
    int g16 = idx & 63;
    int kb  = g16 >> 1;          // 32-float k-block
    int hi  = g16 & 1;           // which 16 within the block
    int rb  = R >> 7, r = R & 127;
    const float4* ip = (const float4*)in + (size_t)idx * 4;
    float4 v0 = ip[0], v1 = ip[1], v2 = ip[2], v3 = ip[3];
    float4 w[4];
    w[0] = make_float4(f2tf32f(v0.x), f2tf32f(v1.x), f2tf32f(v2.x), f2tf32f(v3.x));
    w[1] = make_float4(f2tf32f(v0.y), f2tf32f(v1.y), f2tf32f(v2.y), f2tf32f(v3.y));
    w[2] = make_float4(f2tf32f(v0.z), f2tf32f(v1.z), f2tf32f(v2.z), f2tf32f(v3.z));
    w[3] = make_float4(f2tf32f(v0.w), f2tf32f(v1.w), f2tf32f(v2.w), f2tf32f(v3.w));
    float4* op = (float4*)out + ((size_t)(rb * 32 + kb)) * 1024 + r * 8;
    const int par = (r & 1) * 4;
    #pragma unroll
    for (int t = 0; t < 4; t++)
        op[(hi * 4 + t) ^ par] = w[t];
}

// ---------------------------------------------------------------------------
// prep_kv (unchanged from R8)
// ---------------------------------------------------------------------------
__global__ void prep_kv(const float* __restrict__ qkv,
                        float* __restrict__ kr, float* __restrict__ vt)
{
    int idx = blockIdx.x * blockDim.x + threadIdx.x;
    int n   = idx & (Nn - 1);
    int c16 = (idx >> 11) & 3;
    int bh  = idx >> 13;
    int b   = bh >> 4, h = bh & 15;

    const float* src = qkv + ((size_t)(b * Nn + n)) * D3 + h * DHh + c16 * 16;
    {
        const float4* kp = (const float4*)(src + Dd);
        float4 v0 = kp[0], v1 = kp[1], v2 = kp[2], v3 = kp[3];
        float4* kd = (float4*)(kr + (((size_t)bh * Nn + n)) * 64 + c16 * 16);
        kd[0] = make_float4(f2tf32f(v0.x), f2tf32f(v1.x), f2tf32f(v2.x), f2tf32f(v3.x));
        kd[1] = make_float4(f2tf32f(v0.y), f2tf32f(v1.y), f2tf32f(v2.y), f2tf32f(v3.y));
        kd[2] = make_float4(f2tf32f(v0.z), f2tf32f(v1.z), f2tf32f(v2.z), f2tf32f(v3.z));
        kd[3] = make_float4(f2tf32f(v0.w), f2tf32f(v1.w), f2tf32f(v2.w), f2tf32f(v3.w));
    }
    {
        const float* vsrc = src + 2 * Dd;
        int npm = (n & ~15) + 4 * (n & 3) + ((n >> 2) & 3);
        float* vd = vt + (((size_t)bh * 64 + c16 * 16)) * Nn + npm;
        #pragma unroll
        for (int i = 0; i < 16; i++)
            vd[(size_t)i * Nn] = f2tf32f(vsrc[i]);
    }
}

// ---------------------------------------------------------------------------
// GEMM v6: C[M,N] = A @ B^T + bias. A/B pre-tiled (16KB chunks, swizzled).
// Staging: 2 x cp.async.bulk per 32-k chunk into a 3-buffer mbarrier
// pipeline (issued by thread 0). Compute: mma.sync tf32, warp tile 32x64.
// Dynamic smem: 3 x 32KB = 96KB.
// ---------------------------------------------------------------------------
__global__ __launch_bounds__(256, 2) void tgemm_v6(
    const float4* __restrict__ A, const float4* __restrict__ B,
    const float* __restrict__ bias, float* __restrict__ C, int N)
{
    extern __shared__ float4 gsm[];          // 3 buffers x 2048 float4
    __shared__ uint64_t mbars[3];

    const int tid  = threadIdx.x;
    const int lane = tid & 31;
    const int w    = tid >> 5;
    const int qr   = lane >> 2;
    const int qc   = lane & 3;
    const int wm   = w & 3;
    const int wn   = w >> 2;
    const int nb   = blockIdx.x;
    const int mb   = blockIdx.y;

    uint32_t mb0 = (uint32_t)__cvta_generic_to_shared(mbars);
    if (tid == 0)
        for (int s = 0; s < 3; s++) mbar_init(mb0 + s * 8, 1);
    __syncthreads();

    const float4* Atile = A + (size_t)mb * 32 * 1024;  // 32 chunks of 1024 f4
    const float4* Btile = B + (size_t)nb * 32 * 1024;

    uint32_t sdst[3];
    #pragma unroll
    for (int s = 0; s < 3; s++)
        sdst[s] = (uint32_t)__cvta_generic_to_shared(gsm + s * 2048);

    if (tid == 0) {
        #pragma unroll
        for (int s = 0; s < 3; s++) {
            mbar_expect_tx(mb0 + s * 8, 32768);
            bulk_g2s(sdst[s],         Atile + s * 1024, 16384, mb0 + s * 8);
            bulk_g2s(sdst[s] + 16384, Btile + s * 1024, 16384, mb0 + s * 8);
        }
    }

    float acc[2][8][4];
    #pragma unroll
    for (int f = 0; f < 2; f++)
        #pragma unroll
        for (int nt = 0; nt < 8; nt++)
            #pragma unroll
            for (int i = 0; i < 4; i++) acc[f][nt][i] = 0.f;

    const int par = (qr & 1) * 4;
    const int cx0 = qc ^ par;
    const int cx1 = (4 + qc) ^ par;

    int bsel = 0;
    #pragma unroll 1
    for (int ch = 0; ch < 32; ch++) {
        mbar_wait(mb0 + bsel * 8, (ch / 3) & 1);

        const float4* buf = gsm + bsel * 2048;
        const float4* Ap  = buf + (wm * 32 + qr) * 8;
        const float4* Bp  = buf + 1024 + (wn * 64 + qr) * 8;

        #pragma unroll
        for (int half = 0; half < 2; half++) {
            const int cx = half ? cx1 : cx0;
            float4 A00 = Ap[cx];
            float4 A01 = Ap[64 + cx];
            float4 A10 = Ap[128 + cx];
            float4 A11 = Ap[192 + cx];
            #pragma unroll
            for (int nt = 0; nt < 8; nt++) {
                float4 bv = Bp[nt * 64 + cx];
                mma_tf32(acc[0][nt][0], acc[0][nt][1], acc[0][nt][2], acc[0][nt][3],
                         __float_as_uint(A00.x), __float_as_uint(A01.x),
                         __float_as_uint(A00.y), __float_as_uint(A01.y),
                         __float_as_uint(bv.x),  __float_as_uint(bv.y));
                mma_tf32(acc[1][nt][0], acc[1][nt][1], acc[1][nt][2], acc[1][nt][3],
                         __float_as_uint(A10.x), __float_as_uint(A11.x),
                         __float_as_uint(A10.y), __float_as_uint(A11.y),
                         __float_as_uint(bv.x),  __float_as_uint(bv.y));
                mma_tf32(acc[0][nt][0], acc[0][nt][1], acc[0][nt][2], acc[0][nt][3],
                         __float_as_uint(A00.z), __float_as_uint(A01.z),
                         __float_as_uint(A00.w), __float_as_uint(A01.w),
                         __float_as_uint(bv.z),  __float_as_uint(bv.w));
                mma_tf32(acc[1][nt][0], acc[1][nt][1], acc[1][nt][2], acc[1][nt][3],
                         __float_as_uint(A10.z), __float_as_uint(A11.z),
                         __float_as_uint(A10.w), __float_as_uint(A11.w),
                         __float_as_uint(bv.z),  __float_as_uint(bv.w));
            }
        }

        __syncthreads();   // all warps done with this buffer
        if (tid == 0 && ch + 3 < 32) {
            mbar_expect_tx(mb0 + bsel * 8, 32768);
            bulk_g2s(sdst[bsel],         Atile + (size_t)(ch + 3) * 1024,
                     16384, mb0 + bsel * 8);
            bulk_g2s(sdst[bsel] + 16384, Btile + (size_t)(ch + 3) * 1024,
                     16384, mb0 + bsel * 8);
        }
        bsel = (bsel == 2) ? 0 : bsel + 1;
    }

    // epilogue
    #pragma unroll
    for (int f = 0; f < 2; f++) {
        const int r = mb * 128 + wm * 32 + f * 16 + qr;
        float* Crow0 = C + (size_t)r * N + nb * 128 + wn * 64;
        float* Crow1 = C + (size_t)(r + 8) * N + nb * 128 + wn * 64;
        #pragma unroll
        for (int nt = 0; nt < 8; nt++) {
            const int c = nt * 8 + qc * 2;
            float2 bv = *(const float2*)&bias[nb * 128 + wn * 64 + c];
            *(float2*)&Crow0[c] = make_float2(acc[f][nt][0] + bv.x,
                                              acc[f][nt][1] + bv.y);
            *(float2*)&Crow1[c] = make_float2(acc[f][nt][2] + bv.x,
                                              acc[f][nt][3] + bv.y);
        }
    }
}

// ---------------------------------------------------------------------------
// Flash attention (R8 machinery); epilogue writes the tiled+swizzled layout
// tgemm_v6 consumes.
// ---------------------------------------------------------------------------
__global__ __launch_bounds__(256) void flash_attn_v2(
    const float* __restrict__ qkv, const float* __restrict__ kr,
    const float* __restrict__ vt, float* __restrict__ attnr)
{
    extern __shared__ float4 dsm[];
    constexpr int TILE4 = 64 * 20;
    constexpr float QSCALE = 0.125f * 1.44269504088896341f;

    const int tid  = threadIdx.x;
    const int lane = tid & 31;
    const int w    = tid >> 5;
    const int qr   = lane >> 2;
    const int qc   = lane & 3;
    const int h    = blockIdx.y;
    const int b    = blockIdx.z;
    const int q0   = blockIdx.x * 128;
    const int row0 = w * 16;
    const int bh   = b * Hh + h;

    uint32_t Qa[8][4];
    {
        const float* qb    = qkv + ((size_t)(b * Nn + q0)) * D3 + h * DHh;
        const float* qrow0 = qb + (size_t)(row0 + qr) * D3;
        const float* qrow1 = qb + (size_t)(row0 + qr + 8) * D3;
        #pragma unroll
        for (int k = 0; k < 8; k++) {
            Qa[k][0] = f2tf32(qrow0[k * 8 + qc]     * QSCALE);
            Qa[k][1] = f2tf32(qrow1[k * 8 + qc]     * QSCALE);
            Qa[k][2] = f2tf32(qrow0[k * 8 + qc + 4] * QSCALE);
            Qa[k][3] = f2tf32(qrow1[k * 8 + qc + 4] * QSCALE);
        }
    }

    float O[8][4];
    #pragma unroll
    for (int nt = 0; nt < 8; nt++)
        #pragma unroll
        for (int i = 0; i < 4; i++) O[nt][i] = 0.f;
    float mA = -1e30f, mB = -1e30f, lA = 0.f, lB = 0.f;

    const int sr = tid >> 2;
    const float* gk = kr + ((size_t)bh * Nn + sr) * 64 + (tid & 3) * 16;
    const float* gv = vt + ((size_t)bh * 64 + sr) * Nn + (tid & 3) * 16;

    uint32_t kdst[2], vdst[2];
    #pragma unroll
    for (int s = 0; s < 2; s++) {
        kdst[s] = (uint32_t)__cvta_generic_to_shared(
            &dsm[s * 2 * TILE4 + sr * 20 + (tid & 3) * 4]);
        vdst[s] = (uint32_t)__cvta_generic_to_shared(
            &dsm[s * 2 * TILE4 + TILE4 + sr * 20 + (tid & 3) * 4]);
    }

    auto stage_tile = [&](int t, int s) {
        const float* ks = gk + (size_t)t * 4096;
        const float* vs = gv + (size_t)t * 64;
        #pragma unroll
        for (int j = 0; j < 4; j++) {
            cp_async16(kdst[s] + 16 * j, ks + 4 * j);
            cp_async16(vdst[s] + 16 * j, vs + 4 * j);
        }
        asm volatile("cp.async.commit_group;\n");
    };

    stage_tile(0, 0);
    stage_tile(1, 1);

    const int NT = Nn / 64;
    for (int t = 0; t < NT; t++) {
        asm volatile("cp.async.wait_group %0;\n" :: "n"(1));
        __syncthreads();

        const float4* Kp = dsm + (t & 1) * 2 * TILE4;
        const float4* Vp = Kp + TILE4;

        float S[8][4];
        #pragma unroll
        for (int nt = 0; nt < 8; nt++) {
            const float4* kp = Kp + (nt * 8 + qr) * 20 + qc;
            float4 k0 = kp[0], k1 = kp[4], k2 = kp[8], k3 = kp[12];
            float c0 = 0.f, c1 = 0.f, c2 = 0.f, c3 = 0.f;
            mma_tf32(c0,c1,c2,c3, Qa[0][0],Qa[0][1],Qa[0][2],Qa[0][3],
                     __float_as_uint(k0.x), __float_as_uint(k0.y));
            mma_tf32(c0,c1,c2,c3, Qa[1][0],Qa[1][1],Qa[1][2],Qa[1][3],
                     __float_as_uint(k0.z), __float_as_uint(k0.w));
            mma_tf32(c0,c1,c2,c3, Qa[2][0],Qa[2][1],Qa[2][2],Qa[2][3],
                     __float_as_uint(k1.x), __float_as_uint(k1.y));
            mma_tf32(c0,c1,c2,c3, Qa[3][0],Qa[3][1],Qa[3][2],Qa[3][3],
                     __float_as_uint(k1.z), __float_as_uint(k1.w));
            mma_tf32(c0,c1,c2,c3, Qa[4][0],Qa[4][1],Qa[4][2],Qa[4][3],
                     __float_as_uint(k2.x), __float_as_uint(k2.y));
            mma_tf32(c0,c1,c2,c3, Qa[5][0],Qa[5][1],Qa[5][2],Qa[5][3],
                     __float_as_uint(k2.z), __float_as_uint(k2.w));
            mma_tf32(c0,c1,c2,c3, Qa[6][0],Qa[6][1],Qa[6][2],Qa[6][3],
                     __float_as_uint(k3.x), __float_as_uint(k3.y));
            mma_tf32(c0,c1,c2,c3, Qa[7][0],Qa[7][1],Qa[7][2],Qa[7][3],
                     __float_as_uint(k3.z), __float_as_uint(k3.w));
            S[nt][0] = c0; S[nt][1] = c1; S[nt][2] = c2; S[nt][3] = c3;
        }

        float cmA = -1e30f, cmB = -1e30f;
        #pragma unroll
        for (int nt = 0; nt < 8; nt++) {
            cmA = fmaxf(cmA, fmaxf(S[nt][0], S[nt][1]));
            cmB = fmaxf(cmB, fmaxf(S[nt][2], S[nt][3]));
        }
        cmA = fmaxf(cmA, __shfl_xor_sync(0xffffffffu, cmA, 1));
        cmA = fmaxf(cmA, __shfl_xor_sync(0xffffffffu, cmA, 2));
        cmB = fmaxf(cmB, __shfl_xor_sync(0xffffffffu, cmB, 1));
        cmB = fmaxf(cmB, __shfl_xor_sync(0xffffffffu, cmB, 2));

        const float mnA = fmaxf(mA, cmA), mnB = fmaxf(mB, cmB);
        const float corrA = exp2f(mA - mnA), corrB = exp2f(mB - mnB);
        #pragma unroll
        for (int nt = 0; nt < 8; nt++) {
            O[nt][0] *= corrA; O[nt][1] *= corrA;
            O[nt][2] *= corrB; O[nt][3] *= corrB;
        }

        uint32_t pA[8][4];
        float psA = 0.f, psB = 0.f;
        {
            const int quadbase = lane & ~3;
            const int s0l = quadbase | (qc >> 1);
            const int s1l = s0l + 2;
            const bool odd = qc & 1;
            #pragma unroll
            for (int ks = 0; ks < 8; ks++) {
                float p0 = exp2f(S[ks][0] - mnA);
                float p1 = exp2f(S[ks][1] - mnA);
                float p2 = exp2f(S[ks][2] - mnB);
                float p3 = exp2f(S[ks][3] - mnB);
                psA += p0 + p1;
                psB += p2 + p3;

                float g00 = __shfl_sync(0xffffffffu, p0, s0l);
                float g01 = __shfl_sync(0xffffffffu, p1, s0l);
                float g20 = __shfl_sync(0xffffffffu, p2, s0l);
                float g21 = __shfl_sync(0xffffffffu, p3, s0l);
                float h00 = __shfl_sync(0xffffffffu, p0, s1l);
                float h01 = __shfl_sync(0xffffffffu, p1, s1l);
                float h20 = __shfl_sync(0xffffffffu, p2, s1l);
                float h21 = __shfl_sync(0xffffffffu, p3, s1l);

                pA[ks][0] = f2tf32(odd ? g01 : g00);
                pA[ks][1] = f2tf32(odd ? g21 : g20);
                pA[ks][2] = f2tf32(odd ? h01 : h00);
                pA[ks][3] = f2tf32(odd ? h21 : h20);
            }
        }
        psA += __shfl_xor_sync(0xffffffffu, psA, 1);
        psA += __shfl_xor_sync(0xffffffffu, psA, 2);
        psB += __shfl_xor_sync(0xffffffffu, psB, 1);
        psB += __shfl_xor_sync(0xffffffffu, psB, 2);
        lA = lA * corrA + psA; mA = mnA;
        lB = lB * corrB + psB; mB = mnB;

        #pragma unroll
        for (int nt = 0; nt < 8; nt++) {
            const float4* vp = Vp + (nt * 8 + qr) * 20 + qc;
            float4 v0 = vp[0], v1 = vp[4], v2 = vp[8], v3 = vp[12];
            mma_tf32a(O[nt], pA[0], __float_as_uint(v0.x), __float_as_uint(v0.y));
            mma_tf32a(O[nt], pA[1], __float_as_uint(v0.z), __float_as_uint(v0.w));
            mma_tf32a(O[nt], pA[2], __float_as_uint(v1.x), __float_as_uint(v1.y));
            mma_tf32a(O[nt], pA[3], __float_as_uint(v1.z), __float_as_uint(v1.w));
            mma_tf32a(O[nt], pA[4], __float_as_uint(v2.x), __float_as_uint(v2.y));
            mma_tf32a(O[nt], pA[5], __float_as_uint(v2.z), __float_as_uint(v2.w));
            mma_tf32a(O[nt], pA[6], __float_as_uint(v3.x), __float_as_uint(v3.y));
            mma_tf32a(O[nt], pA[7], __float_as_uint(v3.z), __float_as_uint(v3.w));
        }

        __syncthreads();
        if (t + 2 < NT) stage_tile(t + 2, t & 1);
        else asm volatile("cp.async.commit_group;\n");
    }

    // epilogue: write tiled + repacked + swizzled layout for tgemm_v6
    const float invA = 1.f / lA, invB = 1.f / lB;
    const int bq = b * Nn + q0;
    #pragma unroll
    for (int half = 0; half < 2; half++) {
        const int R  = bq + row0 + qr + half * 8;
        const int rb = R >> 7, r = R & 127;
        const int par = (r & 1) * 4;
        float* tbase = attnr + ((size_t)rb * 32) * 4096 + r * 32;
        #pragma unroll
        for (int nt = 0; nt < 8; nt++) {
            #pragma unroll
            for (int e = 0; e < 2; e++) {
                const int j   = h * 64 + nt * 8 + qc * 2 + e;
                const int kb  = j >> 5;
                const int hi  = (j >> 4) & 1;
                const int j16 = j & 15;
                const int g   = hi * 4 + (j16 & 3);
                const int pos = j16 >> 2;
                float v = (half == 0) ? O[nt][e] * invA : O[nt][2 + e] * invB;
                tbase[(size_t)kb * 4096 + (g ^ par) * 4 + pos] = f2tf32f(v);
            }
        }
    }
}

// ---------------------------------------------------------------------------
// Host launcher
// ---------------------------------------------------------------------------
extern "C" void kernel_launch(void* const* d_in, const int* in_sizes, int n_in,
                              void* d_out, int out_size)
{
    const float* x     = (const float*)d_in[0];
    const float* W_w   = (const float*)d_in[1];
    const float* W_b   = (const float*)d_in[2];
    const float* out_w = (const float*)d_in[3];
    const float* out_b = (const float*)d_in[4];

    float *qkv, *xr, *wwr, *owr, *attnr, *kr, *vt;
    cudaGetSymbolAddress((void**)&qkv,   g_qkv);
    cudaGetSymbolAddress((void**)&xr,    g_xr);
    cudaGetSymbolAddress((void**)&wwr,   g_wwr);
    cudaGetSymbolAddress((void**)&owr,   g_owr);
    cudaGetSymbolAddress((void**)&attnr, g_attnr);
    cudaGetSymbolAddress((void**)&kr,    g_kr);
    cudaGetSymbolAddress((void**)&vt,    g_vt);

    const int M = Bb * Nn;                        // 4096
    const int GEMM_SMEM = 3 * 2048 * 16;          // 96 KB
    const int ATTN_SMEM = 2 * 2 * 64 * 20 * 16;   // 80 KB

    cudaFuncSetAttribute(tgemm_v6,
                         cudaFuncAttributeMaxDynamicSharedMemorySize, GEMM_SMEM);
    cudaFuncSetAttribute(flash_attn_v2,
                         cudaFuncAttributeMaxDynamicSharedMemorySize, ATTN_SMEM);

    // pre-pass: round + tile/repack/swizzle GEMM operands
    repack_tiles<<<M * 64 / 256,  256>>>(x,     xr,  M);
    repack_tiles<<<D3 * 64 / 256, 256>>>(W_w,   wwr, D3);
    repack_tiles<<<Dd * 64 / 256, 256>>>(out_w, owr, Dd);

    // qkv = x @ W_w^T + W_b
    tgemm_v6<<<dim3(D3 / 128, M / 128), 256, GEMM_SMEM>>>(
        (const float4*)xr, (const float4*)wwr, W_b, qkv, D3);

    // prep K/V layouts for attention
    prep_kv<<<(Bb * Hh * 4 * Nn) / 256, 256>>>(qkv, kr, vt);

    // attention -> attnr (tiled layout)
    flash_attn_v2<<<dim3(Nn / 128, Hh, Bb), 256, ATTN_SMEM>>>(qkv, kr, vt, attnr);

    // out = attn @ out_w^T + out_b
    tgemm_v6<<<dim3(Dd / 128, M / 128), 256, GEMM_SMEM>>>(
        (const float4*)attnr, (const float4*)owr, out_b, (float*)d_out, Dd);
}

// round 11
// speedup vs baseline: 1.3232x; 1.2021x over previous
#include <cuda_runtime.h>
#include <math.h>
#include <stdint.h>

// Problem constants
constexpr int Bb  = 2;
constexpr int Nn  = 2048;
constexpr int Dd  = 1024;
constexpr int Hh  = 16;
constexpr int DHh = 64;
constexpr int D3  = 3 * Dd;   // 3072

// Scratch (allocation-free rule: __device__ globals)
__device__ float g_qkv[Bb * Nn * D3];
__device__ float g_xr[Bb * Nn * Dd];      // x tiles (rounded+repacked+swizzled)
__device__ float g_wwr[D3 * Dd];          // W_w tiles
__device__ float g_owr[Dd * Dd];          // out_w tiles
__device__ float g_attnr[Bb * Nn * Dd];   // attn tiles (written by attention)
__device__ float g_kr[Bb * Hh * Nn * DHh];   // K tiles: [bh][t][64r][64c]
__device__ float g_vt[Bb * Hh * DHh * Nn];   // V tiles: [bh][t][64dh][64key]

// ---------------------------------------------------------------------------
// helpers
// ---------------------------------------------------------------------------
__device__ __forceinline__ uint32_t f2tf32(float x) {
    uint32_t r;
    asm("cvt.rna.tf32.f32 %0, %1;" : "=r"(r) : "f"(x));
    return r;
}
__device__ __forceinline__ float f2tf32f(float x) {
    return __uint_as_float(f2tf32(x));
}

__device__ __forceinline__ void mma_tf32(
    float& c0, float& c1, float& c2, float& c3,
    uint32_t a0, uint32_t a1, uint32_t a2, uint32_t a3,
    uint32_t b0, uint32_t b1)
{
    asm volatile(
        "mma.sync.aligned.m16n8k8.row.col.f32.tf32.tf32.f32 "
        "{%0,%1,%2,%3}, {%4,%5,%6,%7}, {%8,%9}, {%0,%1,%2,%3};\n"
        : "+f"(c0), "+f"(c1), "+f"(c2), "+f"(c3)
        : "r"(a0), "r"(a1), "r"(a2), "r"(a3), "r"(b0), "r"(b1));
}
__device__ __forceinline__ void mma_tf32a(
    float* c, const uint32_t* a, uint32_t b0, uint32_t b1)
{
    mma_tf32(c[0], c[1], c[2], c[3], a[0], a[1], a[2], a[3], b0, b1);
}

// mbarrier + bulk-async
__device__ __forceinline__ void mbar_init(uint32_t mbar, uint32_t cnt) {
    asm volatile("mbarrier.init.shared.b64 [%0], %1;" :: "r"(mbar), "r"(cnt)
                 : "memory");
}
__device__ __forceinline__ void mbar_expect_tx(uint32_t mbar, uint32_t bytes) {
    asm volatile("mbarrier.arrive.expect_tx.shared.b64 _, [%0], %1;"
                 :: "r"(mbar), "r"(bytes) : "memory");
}
__device__ __forceinline__ void mbar_wait(uint32_t mbar, uint32_t parity) {
    asm volatile(
        "{\n\t.reg .pred P;\n\t"
        "W%=:\n\t"
        "mbarrier.try_wait.parity.shared.b64 P, [%0], %1;\n\t"
        "@!P bra W%=;\n\t}"
        :: "r"(mbar), "r"(parity) : "memory");
}
__device__ __forceinline__ void bulk_g2s(uint32_t dst, const void* src,
                                         uint32_t bytes, uint32_t mbar) {
    asm volatile(
        "cp.async.bulk.shared::cta.global.mbarrier::complete_tx::bytes "
        "[%0], [%1], %2, [%3];"
        :: "r"(dst), "l"(src), "r"(bytes), "r"(mbar) : "memory");
}

// ---------------------------------------------------------------------------
// repack_tiles: round to tf32; contiguous 16KB chunks [rb][kb] of 128 rows x
// 32 floats; 4x4 repack within 16-groups; float4 col xor (row&1)*4.
// ---------------------------------------------------------------------------
__global__ void repack_tiles(const float* __restrict__ in,
                             float* __restrict__ out, int nrows)
{
    int idx = blockIdx.x * blockDim.x + threadIdx.x;
    if (idx >= nrows * 64) return;
    int R   = idx >> 6;
    int g16 = idx & 63;
    int kb  = g16 >> 1;
    int hi  = g16 & 1;
    int rb  = R >> 7, r = R & 127;
    const float4* ip = (const float4*)in + (size_t)idx * 4;
    float4 v0 = ip[0], v1 = ip[1], v2 = ip[2], v3 = ip[3];
    float4 w[4];
    w[0] = make_float4(f2tf32f(v0.x), f2tf32f(v1.x), f2tf32f(v2.x), f2tf32f(v3.x));
    w[1] = make_float4(f2tf32f(v0.y), f2tf32f(v1.y), f2tf32f(v2.y), f2tf32f(v3.y));
    w[2] = make_float4(f2tf32f(v0.z), f2tf32f(v1.z), f2tf32f(v2.z), f2tf32f(v3.z));
    w[3] = make_float4(f2tf32f(v0.w), f2tf32f(v1.w), f2tf32f(v2.w), f2tf32f(v3.w));
    float4* op = (float4*)out + ((size_t)(rb * 32 + kb)) * 1024 + r * 8;
    const int par = (r & 1) * 4;
    #pragma unroll
    for (int t = 0; t < 4; t++)
        op[(hi * 4 + t) ^ par] = w[t];
}

// ---------------------------------------------------------------------------
// prep_kv v2: K and V as contiguous 16KB tiles (64x64) for bulk staging.
//   K tile [bh][t]: row = key n&63 (par=(n&1)*4), cols = dh (4x4 repacked,
//                   float4 col (c16*4+j)^par).
//   V tile [bh][t]: row = dh (par=(dh&1)*4), cols = key (repacked along n,
//                   float4 col fc^par).
// ---------------------------------------------------------------------------
__global__ void prep_kv(const float* __restrict__ qkv,
                        float* __restrict__ kr, float* __restrict__ vt)
{
    int idx = blockIdx.x * blockDim.x + threadIdx.x;
    int n   = idx & (Nn - 1);
    int c16 = (idx >> 11) & 3;
    int bh  = idx >> 13;
    int b   = bh >> 4, h = bh & 15;
    const int t = n >> 6;
    const int r = n & 63;

    const float* src = qkv + ((size_t)(b * Nn + n)) * D3 + h * DHh + c16 * 16;

    // K
    {
        const float4* kp = (const float4*)(src + Dd);
        float4 v0 = kp[0], v1 = kp[1], v2 = kp[2], v3 = kp[3];
        float4 w[4];
        w[0] = make_float4(f2tf32f(v0.x), f2tf32f(v1.x), f2tf32f(v2.x), f2tf32f(v3.x));
        w[1] = make_float4(f2tf32f(v0.y), f2tf32f(v1.y), f2tf32f(v2.y), f2tf32f(v3.y));
        w[2] = make_float4(f2tf32f(v0.z), f2tf32f(v1.z), f2tf32f(v2.z), f2tf32f(v3.z));
        w[3] = make_float4(f2tf32f(v0.w), f2tf32f(v1.w), f2tf32f(v2.w), f2tf32f(v3.w));
        float4* kd = (float4*)(kr + (((size_t)bh * 32 + t)) * 4096 + r * 64);
        const int par = (r & 1) * 4;
        #pragma unroll
        for (int j = 0; j < 4; j++)
            kd[(c16 * 4 + j) ^ par] = w[j];
    }

    // V (transpose into tile)
    {
        const float* vsrc = src + 2 * Dd;
        const int fc  = ((n >> 4) & 3) * 4 + (n & 3);   // logical float4 col
        const int pos = (n >> 2) & 3;
        float* vtile = vt + (((size_t)bh * 32 + t)) * 4096;
        #pragma unroll
        for (int i = 0; i < 16; i++) {
            const int row = c16 * 16 + i;
            const int par = (i & 1) * 4;                // row parity (c16*16 even)
            vtile[(size_t)row * 64 + ((fc ^ par) * 4 + pos)] = f2tf32f(vsrc[i]);
        }
    }
}

// ---------------------------------------------------------------------------
// GEMM v7: C[M,N] = A @ B^T + bias. A/B pre-tiled (16KB chunks, swizzled).
// 3-buffer bulk-copy pipeline with COMPILE-TIME stage indices (3x unroll).
// Compute: mma.sync tf32, warp tile 32x64. Dynamic smem: 96KB.
// ---------------------------------------------------------------------------
__global__ __launch_bounds__(256, 2) void tgemm_v7(
    const float4* __restrict__ A, const float4* __restrict__ B,
    const float* __restrict__ bias, float* __restrict__ C, int N)
{
    extern __shared__ float4 gsm[];          // 3 buffers x 2048 float4
    __shared__ uint64_t mbars[3];

    const int tid  = threadIdx.x;
    const int lane = tid & 31;
    const int w    = tid >> 5;
    const int qr   = lane >> 2;
    const int qc   = lane & 3;
    const int wm   = w & 3;
    const int wn   = w >> 2;
    const int nb   = blockIdx.x;
    const int mb   = blockIdx.y;

    uint32_t mb0 = (uint32_t)__cvta_generic_to_shared(mbars);
    if (tid == 0)
        for (int s = 0; s < 3; s++) mbar_init(mb0 + s * 8, 1);
    __syncthreads();

    const float4* Atile = A + (size_t)mb * 32 * 1024;
    const float4* Btile = B + (size_t)nb * 32 * 1024;

    uint32_t sdst[3];
    #pragma unroll
    for (int s = 0; s < 3; s++)
        sdst[s] = (uint32_t)__cvta_generic_to_shared(gsm + s * 2048);

    if (tid == 0) {
        #pragma unroll
        for (int s = 0; s < 3; s++) {
            mbar_expect_tx(mb0 + s * 8, 32768);
            bulk_g2s(sdst[s],         Atile + s * 1024, 16384, mb0 + s * 8);
            bulk_g2s(sdst[s] + 16384, Btile + s * 1024, 16384, mb0 + s * 8);
        }
    }

    float acc[2][8][4];
    #pragma unroll
    for (int f = 0; f < 2; f++)
        #pragma unroll
        for (int nt = 0; nt < 8; nt++)
            #pragma unroll
            for (int i = 0; i < 4; i++) acc[f][nt][i] = 0.f;

    const int par = (qr & 1) * 4;
    const int cx0 = qc ^ par;
    const int cx1 = (4 + qc) ^ par;
    const int aoff = (wm * 32 + qr) * 8;
    const int boff = 1024 + (wn * 64 + qr) * 8;

    auto do_chunk = [&](const float4* __restrict__ buf) {
        const float4* Ap = buf + aoff;
        const float4* Bp = buf + boff;
        #pragma unroll
        for (int half = 0; half < 2; half++) {
            const int cx = half ? cx1 : cx0;
            float4 A00 = Ap[cx];
            float4 A01 = Ap[64 + cx];
            float4 A10 = Ap[128 + cx];
            float4 A11 = Ap[192 + cx];
            #pragma unroll
            for (int nt = 0; nt < 8; nt++) {
                float4 bv = Bp[nt * 64 + cx];
                mma_tf32(acc[0][nt][0], acc[0][nt][1], acc[0][nt][2], acc[0][nt][3],
                         __float_as_uint(A00.x), __float_as_uint(A01.x),
                         __float_as_uint(A00.y), __float_as_uint(A01.y),
                         __float_as_uint(bv.x),  __float_as_uint(bv.y));
                mma_tf32(acc[1][nt][0], acc[1][nt][1], acc[1][nt][2], acc[1][nt][3],
                         __float_as_uint(A10.x), __float_as_uint(A11.x),
                         __float_as_uint(A10.y), __float_as_uint(A11.y),
                         __float_as_uint(bv.x),  __float_as_uint(bv.y));
                mma_tf32(acc[0][nt][0], acc[0][nt][1], acc[0][nt][2], acc[0][nt][3],
                         __float_as_uint(A00.z), __float_as_uint(A01.z),
                         __float_as_uint(A00.w), __float_as_uint(A01.w),
                         __float_as_uint(bv.z),  __float_as_uint(bv.w));
                mma_tf32(acc[1][nt][0], acc[1][nt][1], acc[1][nt][2], acc[1][nt][3],
                         __float_as_uint(A10.z), __float_as_uint(A11.z),
                         __float_as_uint(A10.w), __float_as_uint(A11.w),
                         __float_as_uint(bv.z),  __float_as_uint(bv.w));
            }
        }
    };

    const float4* An = Atile + 3 * 1024;
    const float4* Bn = Btile + 3 * 1024;

    #pragma unroll 1
    for (int g = 0; g < 11; g++) {
        #pragma unroll
        for (int s = 0; s < 3; s++) {
            const int ch = g * 3 + s;
            if (ch >= 32) break;
            mbar_wait(mb0 + s * 8, g & 1);
            do_chunk(gsm + s * 2048);
            __syncthreads();
            if (tid == 0 && ch + 3 < 32) {
                mbar_expect_tx(mb0 + s * 8, 32768);
                bulk_g2s(sdst[s],         An, 16384, mb0 + s * 8);
                bulk_g2s(sdst[s] + 16384, Bn, 16384, mb0 + s * 8);
            }
            An += 1024; Bn += 1024;
        }
    }

    // epilogue
    #pragma unroll
    for (int f = 0; f < 2; f++) {
        const int r = mb * 128 + wm * 32 + f * 16 + qr;
        float* Crow0 = C + (size_t)r * N + nb * 128 + wn * 64;
        float* Crow1 = C + (size_t)(r + 8) * N + nb * 128 + wn * 64;
        #pragma unroll
        for (int nt = 0; nt < 8; nt++) {
            const int c = nt * 8 + qc * 2;
            float2 bv = *(const float2*)&bias[nb * 128 + wn * 64 + c];
            *(float2*)&Crow0[c] = make_float2(acc[f][nt][0] + bv.x,
                                              acc[f][nt][1] + bv.y);
            *(float2*)&Crow1[c] = make_float2(acc[f][nt][2] + bv.x,
                                              acc[f][nt][3] + bv.y);
        }
    }
}

// ---------------------------------------------------------------------------
// Flash attention v3: K/V tiles staged by cp.async.bulk (2 x 16KB per tile,
// one thread) into a 2-stage mbarrier pipeline. Fragment loads LDS.128 on
// swizzled stride-16 rows. Epilogue writes tiled layout for tgemm_v7.
// Dynamic smem: 2 stages x 32KB = 64KB.
// ---------------------------------------------------------------------------
__global__ __launch_bounds__(256) void flash_attn_v3(
    const float* __restrict__ qkv, const float* __restrict__ kr,
    const float* __restrict__ vt, float* __restrict__ attnr)
{
    extern __shared__ float4 dsm[];          // [stage][Ktile 1024 | Vtile 1024]
    __shared__ uint64_t ambars[2];
    constexpr float QSCALE = 0.125f * 1.44269504088896341f;

    const int tid  = threadIdx.x;
    const int lane = tid & 31;
    const int w    = tid >> 5;
    const int qr   = lane >> 2;
    const int qc   = lane & 3;
    const int h    = blockIdx.y;
    const int b    = blockIdx.z;
    const int q0   = blockIdx.x * 128;
    const int row0 = w * 16;
    const int bh   = b * Hh + h;

    uint32_t amb = (uint32_t)__cvta_generic_to_shared(ambars);
    uint32_t sK0 = (uint32_t)__cvta_generic_to_shared(dsm);
    if (tid == 0) { mbar_init(amb, 1); mbar_init(amb + 8, 1); }
    __syncthreads();

    const float* ktiles = kr + (size_t)bh * 32 * 4096;
    const float* vtiles = vt + (size_t)bh * 32 * 4096;

    if (tid == 0) {
        #pragma unroll
        for (int s = 0; s < 2; s++) {
            mbar_expect_tx(amb + s * 8, 32768);
            bulk_g2s(sK0 + s * 32768,         ktiles + s * 4096, 16384, amb + s * 8);
            bulk_g2s(sK0 + s * 32768 + 16384, vtiles + s * 4096, 16384, amb + s * 8);
        }
    }

    // Q into A-fragments (scaled by dh^-0.5 * log2e)
    uint32_t Qa[8][4];
    {
        const float* qb    = qkv + ((size_t)(b * Nn + q0)) * D3 + h * DHh;
        const float* qrow0 = qb + (size_t)(row0 + qr) * D3;
        const float* qrow1 = qb + (size_t)(row0 + qr + 8) * D3;
        #pragma unroll
        for (int k = 0; k < 8; k++) {
            Qa[k][0] = f2tf32(qrow0[k * 8 + qc]     * QSCALE);
            Qa[k][1] = f2tf32(qrow1[k * 8 + qc]     * QSCALE);
            Qa[k][2] = f2tf32(qrow0[k * 8 + qc + 4] * QSCALE);
            Qa[k][3] = f2tf32(qrow1[k * 8 + qc + 4] * QSCALE);
        }
    }

    float O[8][4];
    #pragma unroll
    for (int nt = 0; nt < 8; nt++)
        #pragma unroll
        for (int i = 0; i < 4; i++) O[nt][i] = 0.f;
    float mA = -1e30f, mB = -1e30f, lA = 0.f, lB = 0.f;

    const int spar = (qr & 1) * 4;          // fragment swizzle parity
    const int s0x  = qc ^ spar;

    for (int t = 0; t < 32; t++) {
        mbar_wait(amb + (t & 1) * 8, (t >> 1) & 1);

        const float4* Kp = dsm + (t & 1) * 2048;
        const float4* Vp = Kp + 1024;

        // ---- S = Q @ K^T ----
        float S[8][4];
        #pragma unroll
        for (int nt = 0; nt < 8; nt++) {
            const float4* kp = Kp + (nt * 8 + qr) * 16;
            float4 k0 = kp[s0x], k1 = kp[s0x ^ 4];
            float4 k2 = kp[8 + s0x], k3 = kp[8 + (s0x ^ 4)];
            float c0 = 0.f, c1 = 0.f, c2 = 0.f, c3 = 0.f;
            mma_tf32(c0,c1,c2,c3, Qa[0][0],Qa[0][1],Qa[0][2],Qa[0][3],
                     __float_as_uint(k0.x), __float_as_uint(k0.y));
            mma_tf32(c0,c1,c2,c3, Qa[1][0],Qa[1][1],Qa[1][2],Qa[1][3],
                     __float_as_uint(k0.z), __float_as_uint(k0.w));
            mma_tf32(c0,c1,c2,c3, Qa[2][0],Qa[2][1],Qa[2][2],Qa[2][3],
                     __float_as_uint(k1.x), __float_as_uint(k1.y));
            mma_tf32(c0,c1,c2,c3, Qa[3][0],Qa[3][1],Qa[3][2],Qa[3][3],
                     __float_as_uint(k1.z), __float_as_uint(k1.w));
            mma_tf32(c0,c1,c2,c3, Qa[4][0],Qa[4][1],Qa[4][2],Qa[4][3],
                     __float_as_uint(k2.x), __float_as_uint(k2.y));
            mma_tf32(c0,c1,c2,c3, Qa[5][0],Qa[5][1],Qa[5][2],Qa[5][3],
                     __float_as_uint(k2.z), __float_as_uint(k2.w));
            mma_tf32(c0,c1,c2,c3, Qa[6][0],Qa[6][1],Qa[6][2],Qa[6][3],
                     __float_as_uint(k3.x), __float_as_uint(k3.y));
            mma_tf32(c0,c1,c2,c3, Qa[7][0],Qa[7][1],Qa[7][2],Qa[7][3],
                     __float_as_uint(k3.z), __float_as_uint(k3.w));
            S[nt][0] = c0; S[nt][1] = c1; S[nt][2] = c2; S[nt][3] = c3;
        }

        // ---- online softmax (base 2) ----
        float cmA = -1e30f, cmB = -1e30f;
        #pragma unroll
        for (int nt = 0; nt < 8; nt++) {
            cmA = fmaxf(cmA, fmaxf(S[nt][0], S[nt][1]));
            cmB = fmaxf(cmB, fmaxf(S[nt][2], S[nt][3]));
        }
        cmA = fmaxf(cmA, __shfl_xor_sync(0xffffffffu, cmA, 1));
        cmA = fmaxf(cmA, __shfl_xor_sync(0xffffffffu, cmA, 2));
        cmB = fmaxf(cmB, __shfl_xor_sync(0xffffffffu, cmB, 1));
        cmB = fmaxf(cmB, __shfl_xor_sync(0xffffffffu, cmB, 2));

        const float mnA = fmaxf(mA, cmA), mnB = fmaxf(mB, cmB);
        const float corrA = exp2f(mA - mnA), corrB = exp2f(mB - mnB);
        #pragma unroll
        for (int nt = 0; nt < 8; nt++) {
            O[nt][0] *= corrA; O[nt][1] *= corrA;
            O[nt][2] *= corrB; O[nt][3] *= corrB;
        }

        // ---- P = exp2(S-mn); transpose C->A layout via quad shuffles ----
        uint32_t pA[8][4];
        float psA = 0.f, psB = 0.f;
        {
            const int quadbase = lane & ~3;
            const int s0l = quadbase | (qc >> 1);
            const int s1l = s0l + 2;
            const bool odd = qc & 1;
            #pragma unroll
            for (int ks = 0; ks < 8; ks++) {
                float p0 = exp2f(S[ks][0] - mnA);
                float p1 = exp2f(S[ks][1] - mnA);
                float p2 = exp2f(S[ks][2] - mnB);
                float p3 = exp2f(S[ks][3] - mnB);
                psA += p0 + p1;
                psB += p2 + p3;

                float g00 = __shfl_sync(0xffffffffu, p0, s0l);
                float g01 = __shfl_sync(0xffffffffu, p1, s0l);
                float g20 = __shfl_sync(0xffffffffu, p2, s0l);
                float g21 = __shfl_sync(0xffffffffu, p3, s0l);
                float h00 = __shfl_sync(0xffffffffu, p0, s1l);
                float h01 = __shfl_sync(0xffffffffu, p1, s1l);
                float h20 = __shfl_sync(0xffffffffu, p2, s1l);
                float h21 = __shfl_sync(0xffffffffu, p3, s1l);

                pA[ks][0] = f2tf32(odd ? g01 : g00);
                pA[ks][1] = f2tf32(odd ? g21 : g20);
                pA[ks][2] = f2tf32(odd ? h01 : h00);
                pA[ks][3] = f2tf32(odd ? h21 : h20);
            }
        }
        psA += __shfl_xor_sync(0xffffffffu, psA, 1);
        psA += __shfl_xor_sync(0xffffffffu, psA, 2);
        psB += __shfl_xor_sync(0xffffffffu, psB, 1);
        psB += __shfl_xor_sync(0xffffffffu, psB, 2);
        lA = lA * corrA + psA; mA = mnA;
        lB = lB * corrB + psB; mB = mnB;

        // ---- O += P @ V ----
        #pragma unroll
        for (int nt = 0; nt < 8; nt++) {
            const float4* vp = Vp + (nt * 8 + qr) * 16;
            float4 v0 = vp[s0x], v1 = vp[s0x ^ 4];
            float4 v2 = vp[8 + s0x], v3 = vp[8 + (s0x ^ 4)];
            mma_tf32a(O[nt], pA[0], __float_as_uint(v0.x), __float_as_uint(v0.y));
            mma_tf32a(O[nt], pA[1], __float_as_uint(v0.z), __float_as_uint(v0.w));
            mma_tf32a(O[nt], pA[2], __float_as_uint(v1.x), __float_as_uint(v1.y));
            mma_tf32a(O[nt], pA[3], __float_as_uint(v1.z), __float_as_uint(v1.w));
            mma_tf32a(O[nt], pA[4], __float_as_uint(v2.x), __float_as_uint(v2.y));
            mma_tf32a(O[nt], pA[5], __float_as_uint(v2.z), __float_as_uint(v2.w));
            mma_tf32a(O[nt], pA[6], __float_as_uint(v3.x), __float_as_uint(v3.y));
            mma_tf32a(O[nt], pA[7], __float_as_uint(v3.z), __float_as_uint(v3.w));
        }

        __syncthreads();          // all warps done with stage t&1
        if (tid == 0 && t + 2 < 32) {
            const int s = t & 1;
            mbar_expect_tx(amb + s * 8, 32768);
            bulk_g2s(sK0 + s * 32768,         ktiles + (size_t)(t + 2) * 4096,
                     16384, amb + s * 8);
            bulk_g2s(sK0 + s * 32768 + 16384, vtiles + (size_t)(t + 2) * 4096,
                     16384, amb + s * 8);
        }
    }

    // epilogue: write tiled + repacked + swizzled layout for tgemm_v7
    const float invA = 1.f / lA, invB = 1.f / lB;
    const int bq = b * Nn + q0;
    #pragma unroll
    for (int half = 0; half < 2; half++) {
        const int R  = bq + row0 + qr + half * 8;
        const int rb = R >> 7, r = R & 127;
        const int par = (r & 1) * 4;
        float* tbase = attnr + ((size_t)rb * 32) * 4096 + r * 32;
        #pragma unroll
        for (int nt = 0; nt < 8; nt++) {
            #pragma unroll
            for (int e = 0; e < 2; e++) {
                const int j   = h * 64 + nt * 8 + qc * 2 + e;
                const int kb  = j >> 5;
                const int hi  = (j >> 4) & 1;
                const int j16 = j & 15;
                const int g   = hi * 4 + (j16 & 3);
                const int pos = j16 >> 2;
                float v = (half == 0) ? O[nt][e] * invA : O[nt][2 + e] * invB;
                tbase[(size_t)kb * 4096 + (g ^ par) * 4 + pos] = f2tf32f(v);
            }
        }
    }
}

// ---------------------------------------------------------------------------
// Host launcher
// ---------------------------------------------------------------------------
extern "C" void kernel_launch(void* const* d_in, const int* in_sizes, int n_in,
                              void* d_out, int out_size)
{
    const float* x     = (const float*)d_in[0];
    const float* W_w   = (const float*)d_in[1];
    const float* W_b   = (const float*)d_in[2];
    const float* out_w = (const float*)d_in[3];
    const float* out_b = (const float*)d_in[4];

    float *qkv, *xr, *wwr, *owr, *attnr, *kr, *vt;
    cudaGetSymbolAddress((void**)&qkv,   g_qkv);
    cudaGetSymbolAddress((void**)&xr,    g_xr);
    cudaGetSymbolAddress((void**)&wwr,   g_wwr);
    cudaGetSymbolAddress((void**)&owr,   g_owr);
    cudaGetSymbolAddress((void**)&attnr, g_attnr);
    cudaGetSymbolAddress((void**)&kr,    g_kr);
    cudaGetSymbolAddress((void**)&vt,    g_vt);

    const int M = Bb * Nn;                        // 4096
    const int GEMM_SMEM = 3 * 2048 * 16;          // 96 KB
    const int ATTN_SMEM = 2 * 2048 * 16;          // 64 KB

    cudaFuncSetAttribute(tgemm_v7,
                         cudaFuncAttributeMaxDynamicSharedMemorySize, GEMM_SMEM);
    cudaFuncSetAttribute(flash_attn_v3,
                         cudaFuncAttributeMaxDynamicSharedMemorySize, ATTN_SMEM);

    // pre-pass: round + tile/repack/swizzle GEMM operands
    repack_tiles<<<M * 64 / 256,  256>>>(x,     xr,  M);
    repack_tiles<<<D3 * 64 / 256, 256>>>(W_w,   wwr, D3);
    repack_tiles<<<Dd * 64 / 256, 256>>>(out_w, owr, Dd);

    // qkv = x @ W_w^T + W_b
    tgemm_v7<<<dim3(D3 / 128, M / 128), 256, GEMM_SMEM>>>(
        (const float4*)xr, (const float4*)wwr, W_b, qkv, D3);

    // prep K/V tile layouts
    prep_kv<<<(Bb * Hh * 4 * Nn) / 256, 256>>>(qkv, kr, vt);

    // attention -> attnr (tiled layout)
    flash_attn_v3<<<dim3(Nn / 128, Hh, Bb), 256, ATTN_SMEM>>>(qkv, kr, vt, attnr);

    // out = attn @ out_w^T + out_b
    tgemm_v7<<<dim3(Dd / 128, M / 128), 256, GEMM_SMEM>>>(
        (const float4*)attnr, (const float4*)owr, out_b, (float*)d_out, Dd);
}

// round 12
// speedup vs baseline: 1.5138x; 1.1440x over previous
#include <cuda_runtime.h>
#include <cuda_fp16.h>
#include <math.h>
#include <stdint.h>

// Problem constants
constexpr int Bb  = 2;
constexpr int Nn  = 2048;
constexpr int Dd  = 1024;
constexpr int Hh  = 16;
constexpr int DHh = 64;
constexpr int D3  = 3 * Dd;   // 3072

// Scratch (allocation-free rule: __device__ globals)
__device__ float g_qkv[Bb * Nn * D3];
__device__ float g_xr[Bb * Nn * Dd];      // x tiles (rounded+repacked+swizzled)
__device__ float g_wwr[D3 * Dd];          // W_w tiles
__device__ float g_owr[Dd * Dd];          // out_w tiles
__device__ float g_attnr[Bb * Nn * Dd];   // attn tiles (written by attention)
__device__ float g_kr[Bb * Hh * Nn * DHh];          // K tiles fp32 [bh][t][64][64]
__device__ uint16_t g_vth[Bb * Hh * 32 * 64 * 72];  // V tiles fp16 [bh][t][dh64][key72]

// ---------------------------------------------------------------------------
// helpers
// ---------------------------------------------------------------------------
__device__ __forceinline__ uint32_t f2tf32(float x) {
    uint32_t r;
    asm("cvt.rna.tf32.f32 %0, %1;" : "=r"(r) : "f"(x));
    return r;
}
__device__ __forceinline__ float f2tf32f(float x) {
    return __uint_as_float(f2tf32(x));
}
// pack two f32 into f16x2: {lo, hi}
__device__ __forceinline__ uint32_t pack_f16x2(float lo, float hi) {
    uint32_t r;
    asm("cvt.rn.f16x2.f32 %0, %1, %2;" : "=r"(r) : "f"(hi), "f"(lo));
    return r;
}

__device__ __forceinline__ void mma_tf32(
    float& c0, float& c1, float& c2, float& c3,
    uint32_t a0, uint32_t a1, uint32_t a2, uint32_t a3,
    uint32_t b0, uint32_t b1)
{
    asm volatile(
        "mma.sync.aligned.m16n8k8.row.col.f32.tf32.tf32.f32 "
        "{%0,%1,%2,%3}, {%4,%5,%6,%7}, {%8,%9}, {%0,%1,%2,%3};\n"
        : "+f"(c0), "+f"(c1), "+f"(c2), "+f"(c3)
        : "r"(a0), "r"(a1), "r"(a2), "r"(a3), "r"(b0), "r"(b1));
}
__device__ __forceinline__ void mma_f16(
    float* c, uint32_t a0, uint32_t a1, uint32_t a2, uint32_t a3,
    uint32_t b0, uint32_t b1)
{
    asm volatile(
        "mma.sync.aligned.m16n8k16.row.col.f32.f16.f16.f32 "
        "{%0,%1,%2,%3}, {%4,%5,%6,%7}, {%8,%9}, {%0,%1,%2,%3};\n"
        : "+f"(c[0]), "+f"(c[1]), "+f"(c[2]), "+f"(c[3])
        : "r"(a0), "r"(a1), "r"(a2), "r"(a3), "r"(b0), "r"(b1));
}

// mbarrier + bulk-async
__device__ __forceinline__ void mbar_init(uint32_t mbar, uint32_t cnt) {
    asm volatile("mbarrier.init.shared.b64 [%0], %1;" :: "r"(mbar), "r"(cnt)
                 : "memory");
}
__device__ __forceinline__ void mbar_expect_tx(uint32_t mbar, uint32_t bytes) {
    asm volatile("mbarrier.arrive.expect_tx.shared.b64 _, [%0], %1;"
                 :: "r"(mbar), "r"(bytes) : "memory");
}
__device__ __forceinline__ void mbar_wait(uint32_t mbar, uint32_t parity) {
    asm volatile(
        "{\n\t.reg .pred P;\n\t"
        "W%=:\n\t"
        "mbarrier.try_wait.parity.shared.b64 P, [%0], %1;\n\t"
        "@!P bra W%=;\n\t}"
        :: "r"(mbar), "r"(parity) : "memory");
}
__device__ __forceinline__ void bulk_g2s(uint32_t dst, const void* src,
                                         uint32_t bytes, uint32_t mbar) {
    asm volatile(
        "cp.async.bulk.shared::cta.global.mbarrier::complete_tx::bytes "
        "[%0], [%1], %2, [%3];"
        :: "r"(dst), "l"(src), "r"(bytes), "r"(mbar) : "memory");
}

// ---------------------------------------------------------------------------
// repack_tiles: round to tf32; contiguous 16KB chunks [rb][kb] of 128 rows x
// 32 floats; 4x4 repack within 16-groups; float4 col xor (row&1)*4.
// ---------------------------------------------------------------------------
__global__ void repack_tiles(const float* __restrict__ in,
                             float* __restrict__ out, int nrows)
{
    int idx = blockIdx.x * blockDim.x + threadIdx.x;
    if (idx >= nrows * 64) return;
    int R   = idx >> 6;
    int g16 = idx & 63;
    int kb  = g16 >> 1;
    int hi  = g16 & 1;
    int rb  = R >> 7, r = R & 127;
    const float4* ip = (const float4*)in + (size_t)idx * 4;
    float4 v0 = ip[0], v1 = ip[1], v2 = ip[2], v3 = ip[3];
    float4 w[4];
    w[0] = make_float4(f2tf32f(v0.x), f2tf32f(v1.x), f2tf32f(v2.x), f2tf32f(v3.x));
    w[1] = make_float4(f2tf32f(v0.y), f2tf32f(v1.y), f2tf32f(v2.y), f2tf32f(v3.y));
    w[2] = make_float4(f2tf32f(v0.z), f2tf32f(v1.z), f2tf32f(v2.z), f2tf32f(v3.z));
    w[3] = make_float4(f2tf32f(v0.w), f2tf32f(v1.w), f2tf32f(v2.w), f2tf32f(v3.w));
    float4* op = (float4*)out + ((size_t)(rb * 32 + kb)) * 1024 + r * 8;
    const int par = (r & 1) * 4;
    #pragma unroll
    for (int t = 0; t < 4; t++)
        op[(hi * 4 + t) ^ par] = w[t];
}

// ---------------------------------------------------------------------------
// prep_kv v3: K as 16KB fp32 tiles (swizzled, for tf32 QK);
//             V as fp16 tiles [dh=64][key stride 72] (for fp16 PV).
// ---------------------------------------------------------------------------
__global__ void prep_kv(const float* __restrict__ qkv,
                        float* __restrict__ kr, uint16_t* __restrict__ vth)
{
    int idx = blockIdx.x * blockDim.x + threadIdx.x;
    int n   = idx & (Nn - 1);
    int c16 = (idx >> 11) & 3;
    int bh  = idx >> 13;
    int b   = bh >> 4, h = bh & 15;
    const int t = n >> 6;
    const int r = n & 63;

    const float* src = qkv + ((size_t)(b * Nn + n)) * D3 + h * DHh + c16 * 16;

    // K tile (fp32 tf32, swizzled for LDS.128)
    {
        const float4* kp = (const float4*)(src + Dd);
        float4 v0 = kp[0], v1 = kp[1], v2 = kp[2], v3 = kp[3];
        float4 w[4];
        w[0] = make_float4(f2tf32f(v0.x), f2tf32f(v1.x), f2tf32f(v2.x), f2tf32f(v3.x));
        w[1] = make_float4(f2tf32f(v0.y), f2tf32f(v1.y), f2tf32f(v2.y), f2tf32f(v3.y));
        w[2] = make_float4(f2tf32f(v0.z), f2tf32f(v1.z), f2tf32f(v2.z), f2tf32f(v3.z));
        w[3] = make_float4(f2tf32f(v0.w), f2tf32f(v1.w), f2tf32f(v2.w), f2tf32f(v3.w));
        float4* kd = (float4*)(kr + (((size_t)bh * 32 + t)) * 4096 + r * 64);
        const int par = (r & 1) * 4;
        #pragma unroll
        for (int j = 0; j < 4; j++)
            kd[(c16 * 4 + j) ^ par] = w[j];
    }

    // V tile (fp16, transposed: row=dh, col=key, row stride 72 halves)
    {
        const float* vsrc = src + 2 * Dd;
        uint16_t* vtile = vth + (((size_t)bh * 32 + t)) * (64 * 72);
        #pragma unroll
        for (int i = 0; i < 16; i++) {
            const int row = c16 * 16 + i;
            __half hv = __float2half_rn(vsrc[i]);
            vtile[(size_t)row * 72 + r] = *(const uint16_t*)&hv;
        }
    }
}

// ---------------------------------------------------------------------------
// GEMM v7 (unchanged from R11): bulk-copy 3-stage pipeline, mma.sync tf32.
// ---------------------------------------------------------------------------
__global__ __launch_bounds__(256, 2) void tgemm_v7(
    const float4* __restrict__ A, const float4* __restrict__ B,
    const float* __restrict__ bias, float* __restrict__ C, int N)
{
    extern __shared__ float4 gsm[];
    __shared__ uint64_t mbars[3];

    const int tid  = threadIdx.x;
    const int lane = tid & 31;
    const int w    = tid >> 5;
    const int qr   = lane >> 2;
    const int qc   = lane & 3;
    const int wm   = w & 3;
    const int wn   = w >> 2;
    const int nb   = blockIdx.x;
    const int mb   = blockIdx.y;

    uint32_t mb0 = (uint32_t)__cvta_generic_to_shared(mbars);
    if (tid == 0)
        for (int s = 0; s < 3; s++) mbar_init(mb0 + s * 8, 1);
    __syncthreads();

    const float4* Atile = A + (size_t)mb * 32 * 1024;
    const float4* Btile = B + (size_t)nb * 32 * 1024;

    uint32_t sdst[3];
    #pragma unroll
    for (int s = 0; s < 3; s++)
        sdst[s] = (uint32_t)__cvta_generic_to_shared(gsm + s * 2048);

    if (tid == 0) {
        #pragma unroll
        for (int s = 0; s < 3; s++) {
            mbar_expect_tx(mb0 + s * 8, 32768);
            bulk_g2s(sdst[s],         Atile + s * 1024, 16384, mb0 + s * 8);
            bulk_g2s(sdst[s] + 16384, Btile + s * 1024, 16384, mb0 + s * 8);
        }
    }

    float acc[2][8][4];
    #pragma unroll
    for (int f = 0; f < 2; f++)
        #pragma unroll
        for (int nt = 0; nt < 8; nt++)
            #pragma unroll
            for (int i = 0; i < 4; i++) acc[f][nt][i] = 0.f;

    const int par = (qr & 1) * 4;
    const int cx0 = qc ^ par;
    const int cx1 = (4 + qc) ^ par;
    const int aoff = (wm * 32 + qr) * 8;
    const int boff = 1024 + (wn * 64 + qr) * 8;

    auto do_chunk = [&](const float4* __restrict__ buf) {
        const float4* Ap = buf + aoff;
        const float4* Bp = buf + boff;
        #pragma unroll
        for (int half = 0; half < 2; half++) {
            const int cx = half ? cx1 : cx0;
            float4 A00 = Ap[cx];
            float4 A01 = Ap[64 + cx];
            float4 A10 = Ap[128 + cx];
            float4 A11 = Ap[192 + cx];
            #pragma unroll
            for (int nt = 0; nt < 8; nt++) {
                float4 bv = Bp[nt * 64 + cx];
                mma_tf32(acc[0][nt][0], acc[0][nt][1], acc[0][nt][2], acc[0][nt][3],
                         __float_as_uint(A00.x), __float_as_uint(A01.x),
                         __float_as_uint(A00.y), __float_as_uint(A01.y),
                         __float_as_uint(bv.x),  __float_as_uint(bv.y));
                mma_tf32(acc[1][nt][0], acc[1][nt][1], acc[1][nt][2], acc[1][nt][3],
                         __float_as_uint(A10.x), __float_as_uint(A11.x),
                         __float_as_uint(A10.y), __float_as_uint(A11.y),
                         __float_as_uint(bv.x),  __float_as_uint(bv.y));
                mma_tf32(acc[0][nt][0], acc[0][nt][1], acc[0][nt][2], acc[0][nt][3],
                         __float_as_uint(A00.z), __float_as_uint(A01.z),
                         __float_as_uint(A00.w), __float_as_uint(A01.w),
                         __float_as_uint(bv.z),  __float_as_uint(bv.w));
                mma_tf32(acc[1][nt][0], acc[1][nt][1], acc[1][nt][2], acc[1][nt][3],
                         __float_as_uint(A10.z), __float_as_uint(A11.z),
                         __float_as_uint(A10.w), __float_as_uint(A11.w),
                         __float_as_uint(bv.z),  __float_as_uint(bv.w));
            }
        }
    };

    const float4* An = Atile + 3 * 1024;
    const float4* Bn = Btile + 3 * 1024;

    #pragma unroll 1
    for (int g = 0; g < 11; g++) {
        #pragma unroll
        for (int s = 0; s < 3; s++) {
            const int ch = g * 3 + s;
            if (ch >= 32) break;
            mbar_wait(mb0 + s * 8, g & 1);
            do_chunk(gsm + s * 2048);
            __syncthreads();
            if (tid == 0 && ch + 3 < 32) {
                mbar_expect_tx(mb0 + s * 8, 32768);
                bulk_g2s(sdst[s],         An, 16384, mb0 + s * 8);
                bulk_g2s(sdst[s] + 16384, Bn, 16384, mb0 + s * 8);
            }
            An += 1024; Bn += 1024;
        }
    }

    #pragma unroll
    for (int f = 0; f < 2; f++) {
        const int r = mb * 128 + wm * 32 + f * 16 + qr;
        float* Crow0 = C + (size_t)r * N + nb * 128 + wn * 64;
        float* Crow1 = C + (size_t)(r + 8) * N + nb * 128 + wn * 64;
        #pragma unroll
        for (int nt = 0; nt < 8; nt++) {
            const int c = nt * 8 + qc * 2;
            float2 bv = *(const float2*)&bias[nb * 128 + wn * 64 + c];
            *(float2*)&Crow0[c] = make_float2(acc[f][nt][0] + bv.x,
                                              acc[f][nt][1] + bv.y);
            *(float2*)&Crow1[c] = make_float2(acc[f][nt][2] + bv.x,
                                              acc[f][nt][3] + bv.y);
        }
    }
}

// ---------------------------------------------------------------------------
// Flash attention v4: tf32 QK^T + fp16 PV (FA2 register-layout trick: S
// C-fragments convert directly to P A-fragments, no shuffles). K fp32 tiles
// + V fp16 tiles staged by cp.async.bulk, 2-stage pipeline.
// Stage = 16KB K + 9216B V = 25600B; 2 stages = 51200B dynamic smem.
// ---------------------------------------------------------------------------
__global__ __launch_bounds__(256) void flash_attn_v4(
    const float* __restrict__ qkv, const float* __restrict__ kr,
    const uint16_t* __restrict__ vth, float* __restrict__ attnr)
{
    extern __shared__ char dsma[];
    __shared__ uint64_t ambars[2];
    constexpr int STAGE_B = 25600;
    constexpr float QSCALE = 0.125f * 1.44269504088896341f;

    const int tid  = threadIdx.x;
    const int lane = tid & 31;
    const int w    = tid >> 5;
    const int qr   = lane >> 2;
    const int qc   = lane & 3;
    const int h    = blockIdx.y;
    const int b    = blockIdx.z;
    const int q0   = blockIdx.x * 128;
    const int row0 = w * 16;
    const int bh   = b * Hh + h;

    uint32_t amb = (uint32_t)__cvta_generic_to_shared(ambars);
    uint32_t sb0 = (uint32_t)__cvta_generic_to_shared(dsma);
    if (tid == 0) { mbar_init(amb, 1); mbar_init(amb + 8, 1); }
    __syncthreads();

    const float*    ktiles = kr  + (size_t)bh * 32 * 4096;
    const uint16_t* vtiles = vth + (size_t)bh * 32 * (64 * 72);

    if (tid == 0) {
        #pragma unroll
        for (int s = 0; s < 2; s++) {
            mbar_expect_tx(amb + s * 8, STAGE_B);
            bulk_g2s(sb0 + s * STAGE_B,         ktiles + s * 4096,      16384,
                     amb + s * 8);
            bulk_g2s(sb0 + s * STAGE_B + 16384, vtiles + s * (64 * 72), 9216,
                     amb + s * 8);
        }
    }

    // Q into tf32 A-fragments (scaled by dh^-0.5 * log2e)
    uint32_t Qa[8][4];
    {
        const float* qb    = qkv + ((size_t)(b * Nn + q0)) * D3 + h * DHh;
        const float* qrow0 = qb + (size_t)(row0 + qr) * D3;
        const float* qrow1 = qb + (size_t)(row0 + qr + 8) * D3;
        #pragma unroll
        for (int k = 0; k < 8; k++) {
            Qa[k][0] = f2tf32(qrow0[k * 8 + qc]     * QSCALE);
            Qa[k][1] = f2tf32(qrow1[k * 8 + qc]     * QSCALE);
            Qa[k][2] = f2tf32(qrow0[k * 8 + qc + 4] * QSCALE);
            Qa[k][3] = f2tf32(qrow1[k * 8 + qc + 4] * QSCALE);
        }
    }

    float O[8][4];
    #pragma unroll
    for (int nt = 0; nt < 8; nt++)
        #pragma unroll
        for (int i = 0; i < 4; i++) O[nt][i] = 0.f;
    float mA = -1e30f, mB = -1e30f, lA = 0.f, lB = 0.f;

    const int spar = (qr & 1) * 4;
    const int s0x  = qc ^ spar;

    for (int t = 0; t < 32; t++) {
        mbar_wait(amb + (t & 1) * 8, (t >> 1) & 1);

        const float4*   Kp = (const float4*)(dsma + (t & 1) * STAGE_B);
        const uint32_t* Vp = (const uint32_t*)(dsma + (t & 1) * STAGE_B + 16384);

        // ---- S = Q @ K^T (tf32) ----
        float S[8][4];
        #pragma unroll
        for (int nt = 0; nt < 8; nt++) {
            const float4* kp = Kp + (nt * 8 + qr) * 16;
            float4 k0 = kp[s0x], k1 = kp[s0x ^ 4];
            float4 k2 = kp[8 + s0x], k3 = kp[8 + (s0x ^ 4)];
            float c0 = 0.f, c1 = 0.f, c2 = 0.f, c3 = 0.f;
            mma_tf32(c0,c1,c2,c3, Qa[0][0],Qa[0][1],Qa[0][2],Qa[0][3],
                     __float_as_uint(k0.x), __float_as_uint(k0.y));
            mma_tf32(c0,c1,c2,c3, Qa[1][0],Qa[1][1],Qa[1][2],Qa[1][3],
                     __float_as_uint(k0.z), __float_as_uint(k0.w));
            mma_tf32(c0,c1,c2,c3, Qa[2][0],Qa[2][1],Qa[2][2],Qa[2][3],
                     __float_as_uint(k1.x), __float_as_uint(k1.y));
            mma_tf32(c0,c1,c2,c3, Qa[3][0],Qa[3][1],Qa[3][2],Qa[3][3],
                     __float_as_uint(k1.z), __float_as_uint(k1.w));
            mma_tf32(c0,c1,c2,c3, Qa[4][0],Qa[4][1],Qa[4][2],Qa[4][3],
                     __float_as_uint(k2.x), __float_as_uint(k2.y));
            mma_tf32(c0,c1,c2,c3, Qa[5][0],Qa[5][1],Qa[5][2],Qa[5][3],
                     __float_as_uint(k2.z), __float_as_uint(k2.w));
            mma_tf32(c0,c1,c2,c3, Qa[6][0],Qa[6][1],Qa[6][2],Qa[6][3],
                     __float_as_uint(k3.x), __float_as_uint(k3.y));
            mma_tf32(c0,c1,c2,c3, Qa[7][0],Qa[7][1],Qa[7][2],Qa[7][3],
                     __float_as_uint(k3.z), __float_as_uint(k3.w));
            S[nt][0] = c0; S[nt][1] = c1; S[nt][2] = c2; S[nt][3] = c3;
        }

        // ---- online softmax (base 2) ----
        float cmA = -1e30f, cmB = -1e30f;
        #pragma unroll
        for (int nt = 0; nt < 8; nt++) {
            cmA = fmaxf(cmA, fmaxf(S[nt][0], S[nt][1]));
            cmB = fmaxf(cmB, fmaxf(S[nt][2], S[nt][3]));
        }
        cmA = fmaxf(cmA, __shfl_xor_sync(0xffffffffu, cmA, 1));
        cmA = fmaxf(cmA, __shfl_xor_sync(0xffffffffu, cmA, 2));
        cmB = fmaxf(cmB, __shfl_xor_sync(0xffffffffu, cmB, 1));
        cmB = fmaxf(cmB, __shfl_xor_sync(0xffffffffu, cmB, 2));

        const float mnA = fmaxf(mA, cmA), mnB = fmaxf(mB, cmB);
        const float corrA = exp2f(mA - mnA), corrB = exp2f(mB - mnB);
        #pragma unroll
        for (int nt = 0; nt < 8; nt++) {
            O[nt][0] *= corrA; O[nt][1] *= corrA;
            O[nt][2] *= corrB; O[nt][3] *= corrB;
        }

        // ---- P = exp2(S-mn) -> fp16 A-fragments (no shuffles);
        //      O += P @ V (fp16 m16n8k16) ----
        float psA = 0.f, psB = 0.f;
        #pragma unroll
        for (int kt = 0; kt < 4; kt++) {
            float q00 = exp2f(S[2*kt][0]   - mnA);
            float q01 = exp2f(S[2*kt][1]   - mnA);
            float q10 = exp2f(S[2*kt][2]   - mnB);
            float q11 = exp2f(S[2*kt][3]   - mnB);
            float r00 = exp2f(S[2*kt+1][0] - mnA);
            float r01 = exp2f(S[2*kt+1][1] - mnA);
            float r10 = exp2f(S[2*kt+1][2] - mnB);
            float r11 = exp2f(S[2*kt+1][3] - mnB);
            psA += q00 + q01 + r00 + r01;
            psB += q10 + q11 + r10 + r11;

            uint32_t a0 = pack_f16x2(q00, q01);   // row qr,   keys 16kt+2qc..+1
            uint32_t a1 = pack_f16x2(q10, q11);   // row qr+8
            uint32_t a2 = pack_f16x2(r00, r01);   // row qr,   keys +8
            uint32_t a3 = pack_f16x2(r10, r11);   // row qr+8

            const uint32_t* vb = Vp + 8 * kt + qc;
            #pragma unroll
            for (int nt = 0; nt < 8; nt++) {
                const uint32_t* vr = vb + (nt * 8 + qr) * 36;
                mma_f16(O[nt], a0, a1, a2, a3, vr[0], vr[4]);
            }
        }
        psA += __shfl_xor_sync(0xffffffffu, psA, 1);
        psA += __shfl_xor_sync(0xffffffffu, psA, 2);
        psB += __shfl_xor_sync(0xffffffffu, psB, 1);
        psB += __shfl_xor_sync(0xffffffffu, psB, 2);
        lA = lA * corrA + psA; mA = mnA;
        lB = lB * corrB + psB; mB = mnB;

        __syncthreads();          // all warps done with stage t&1
        if (tid == 0 && t + 2 < 32) {
            const int s = t & 1;
            mbar_expect_tx(amb + s * 8, STAGE_B);
            bulk_g2s(sb0 + s * STAGE_B,
                     ktiles + (size_t)(t + 2) * 4096, 16384, amb + s * 8);
            bulk_g2s(sb0 + s * STAGE_B + 16384,
                     vtiles + (size_t)(t + 2) * (64 * 72), 9216, amb + s * 8);
        }
    }

    // epilogue: write tiled + repacked + swizzled layout for tgemm_v7
    const float invA = 1.f / lA, invB = 1.f / lB;
    const int bq = b * Nn + q0;
    #pragma unroll
    for (int half = 0; half < 2; half++) {
        const int R  = bq + row0 + qr + half * 8;
        const int rb = R >> 7, r = R & 127;
        const int par = (r & 1) * 4;
        float* tbase = attnr + ((size_t)rb * 32) * 4096 + r * 32;
        #pragma unroll
        for (int nt = 0; nt < 8; nt++) {
            #pragma unroll
            for (int e = 0; e < 2; e++) {
                const int j   = h * 64 + nt * 8 + qc * 2 + e;
                const int kb  = j >> 5;
                const int hi  = (j >> 4) & 1;
                const int j16 = j & 15;
                const int g   = hi * 4 + (j16 & 3);
                const int pos = j16 >> 2;
                float v = (half == 0) ? O[nt][e] * invA : O[nt][2 + e] * invB;
                tbase[(size_t)kb * 4096 + (g ^ par) * 4 + pos] = f2tf32f(v);
            }
        }
    }
}

// ---------------------------------------------------------------------------
// Host launcher
// ---------------------------------------------------------------------------
extern "C" void kernel_launch(void* const* d_in, const int* in_sizes, int n_in,
                              void* d_out, int out_size)
{
    const float* x     = (const float*)d_in[0];
    const float* W_w   = (const float*)d_in[1];
    const float* W_b   = (const float*)d_in[2];
    const float* out_w = (const float*)d_in[3];
    const float* out_b = (const float*)d_in[4];

    float *qkv, *xr, *wwr, *owr, *attnr, *kr;
    uint16_t* vth;
    cudaGetSymbolAddress((void**)&qkv,   g_qkv);
    cudaGetSymbolAddress((void**)&xr,    g_xr);
    cudaGetSymbolAddress((void**)&wwr,   g_wwr);
    cudaGetSymbolAddress((void**)&owr,   g_owr);
    cudaGetSymbolAddress((void**)&attnr, g_attnr);
    cudaGetSymbolAddress((void**)&kr,    g_kr);
    cudaGetSymbolAddress((void**)&vth,   g_vth);

    const int M = Bb * Nn;                        // 4096
    const int GEMM_SMEM = 3 * 2048 * 16;          // 96 KB
    const int ATTN_SMEM = 2 * 25600;              // 51200 B

    cudaFuncSetAttribute(tgemm_v7,
                         cudaFuncAttributeMaxDynamicSharedMemorySize, GEMM_SMEM);
    cudaFuncSetAttribute(flash_attn_v4,
                         cudaFuncAttributeMaxDynamicSharedMemorySize, ATTN_SMEM);

    // pre-pass: round + tile/repack/swizzle GEMM operands
    repack_tiles<<<M * 64 / 256,  256>>>(x,     xr,  M);
    repack_tiles<<<D3 * 64 / 256, 256>>>(W_w,   wwr, D3);
    repack_tiles<<<Dd * 64 / 256, 256>>>(out_w, owr, Dd);

    // qkv = x @ W_w^T + W_b
    tgemm_v7<<<dim3(D3 / 128, M / 128), 256, GEMM_SMEM>>>(
        (const float4*)xr, (const float4*)wwr, W_b, qkv, D3);

    // prep K/V tile layouts
    prep_kv<<<(Bb * Hh * 4 * Nn) / 256, 256>>>(qkv, kr, vth);

    // attention -> attnr (tiled layout)
    flash_attn_v4<<<dim3(Nn / 128, Hh, Bb), 256, ATTN_SMEM>>>(qkv, kr, vth, attnr);

    // out = attn @ out_w^T + out_b
    tgemm_v7<<<dim3(Dd / 128, M / 128), 256, GEMM_SMEM>>>(
        (const float4*)attnr, (const float4*)owr, out_b, (float*)d_out, Dd);
}

// round 15
// speedup vs baseline: 2.0840x; 1.3767x over previous
#include <cuda_runtime.h>
#include <cuda_fp16.h>
#include <math.h>
#include <stdint.h>

// Problem constants
constexpr int Bb  = 2;
constexpr int Nn  = 2048;
constexpr int Dd  = 1024;
constexpr int Hh  = 16;
constexpr int DHh = 64;
constexpr int D3  = 3 * Dd;   // 3072

// Scratch (allocation-free rule: __device__ globals)
__device__ float    g_qkv[Bb * Nn * D3];
__device__ uint16_t g_xr[Bb * Nn * Dd];        // x fp16 tiles
__device__ uint16_t g_wwr[D3 * Dd];            // W_w fp16 tiles
__device__ uint16_t g_owr[Dd * Dd];            // out_w fp16 tiles
__device__ uint16_t g_attnrh[Bb * Nn * Dd];    // attn fp16 tiles
__device__ uint16_t g_krh[Bb * Hh * Nn * DHh];       // K fp16 tiles [bh][t][64][64]
__device__ uint16_t g_vth[Bb * Hh * 32 * 64 * 72];   // V fp16 tiles [bh][t][64dh][72key]

// ---------------------------------------------------------------------------
// helpers
// ---------------------------------------------------------------------------
// pack two f32 into f16x2: lo -> low 16 bits
__device__ __forceinline__ uint32_t pack_f16x2(float lo, float hi) {
    uint32_t r;
    asm("cvt.rn.f16x2.f32 %0, %1, %2;" : "=r"(r) : "f"(hi), "f"(lo));
    return r;
}

__device__ __forceinline__ void mma_f16(
    float* c, uint32_t a0, uint32_t a1, uint32_t a2, uint32_t a3,
    uint32_t b0, uint32_t b1)
{
    asm volatile(
        "mma.sync.aligned.m16n8k16.row.col.f32.f16.f16.f32 "
        "{%0,%1,%2,%3}, {%4,%5,%6,%7}, {%8,%9}, {%0,%1,%2,%3};\n"
        : "+f"(c[0]), "+f"(c[1]), "+f"(c[2]), "+f"(c[3])
        : "r"(a0), "r"(a1), "r"(a2), "r"(a3), "r"(b0), "r"(b1));
}

// mbarrier + bulk-async
__device__ __forceinline__ void mbar_init(uint32_t mbar, uint32_t cnt) {
    asm volatile("mbarrier.init.shared.b64 [%0], %1;" :: "r"(mbar), "r"(cnt)
                 : "memory");
}
__device__ __forceinline__ void mbar_expect_tx(uint32_t mbar, uint32_t bytes) {
    asm volatile("mbarrier.arrive.expect_tx.shared.b64 _, [%0], %1;"
                 :: "r"(mbar), "r"(bytes) : "memory");
}
__device__ __forceinline__ void mbar_wait(uint32_t mbar, uint32_t parity) {
    asm volatile(
        "{\n\t.reg .pred P;\n\t"
        "W%=:\n\t"
        "mbarrier.try_wait.parity.shared.b64 P, [%0], %1;\n\t"
        "@!P bra W%=;\n\t}"
        :: "r"(mbar), "r"(parity) : "memory");
}
__device__ __forceinline__ void bulk_g2s(uint32_t dst, const void* src,
                                         uint32_t bytes, uint32_t mbar) {
    asm volatile(
        "cp.async.bulk.shared::cta.global.mbarrier::complete_tx::bytes "
        "[%0], [%1], %2, [%3];"
        :: "r"(dst), "l"(src), "r"(bytes), "r"(mbar) : "memory");
}

// ---------------------------------------------------------------------------
// repack_tiles_f16: fp32 [nrows][1024] -> fp16 tiles, contiguous 16KB chunks
// [rb][kb(16)][128 rows][8 uint4]. Per row chunk = 64 halves = 32 words;
// word repack {w, w+4, w+8, w+12} -> one uint4; uint4 col xor (row&1)*4.
// One thread per chunk-row (64 floats).
// ---------------------------------------------------------------------------
__global__ void repack_tiles_f16(const float* __restrict__ in,
                                 uint16_t* __restrict__ out, int nrows)
{
    int idx = blockIdx.x * blockDim.x + threadIdx.x;
    if (idx >= nrows * 16) return;
    const int R  = idx >> 4;
    const int kb = idx & 15;
    const int rb = R >> 7, r = R & 127;
    const int par = (r & 1) * 4;

    const float4* ip = (const float4*)(in + (size_t)R * 1024 + kb * 64);
    uint32_t wb[32];
    #pragma unroll
    for (int j = 0; j < 16; j++) {
        float4 v = ip[j];
        wb[2 * j]     = pack_f16x2(v.x, v.y);
        wb[2 * j + 1] = pack_f16x2(v.z, v.w);
    }
    uint4* op = (uint4*)out + ((size_t)(rb * 16 + kb) * 128 + r) * 8;
    #pragma unroll
    for (int g = 0; g < 2; g++)
        #pragma unroll
        for (int t = 0; t < 4; t++)
            op[(g * 4 + t) ^ par] = make_uint4(wb[g * 16 + t],
                                               wb[g * 16 + 4 + t],
                                               wb[g * 16 + 8 + t],
                                               wb[g * 16 + 12 + t]);
}

// ---------------------------------------------------------------------------
// prep_kv v4: K as 8KB fp16 tiles (word-repacked + swizzled, rows=key);
//             V as fp16 tiles [dh=64][key stride 72].
// ---------------------------------------------------------------------------
__global__ void prep_kv(const float* __restrict__ qkv,
                        uint16_t* __restrict__ krh, uint16_t* __restrict__ vth)
{
    int idx = blockIdx.x * blockDim.x + threadIdx.x;
    int n   = idx & (Nn - 1);
    int c16 = (idx >> 11) & 3;
    int bh  = idx >> 13;
    int b   = bh >> 4, h = bh & 15;
    const int t = n >> 6;
    const int r = n & 63;

    const float* src = qkv + ((size_t)(b * Nn + n)) * D3 + h * DHh + c16 * 16;

    // K tile: row r = key, 32 words of dh; words c16*8 .. c16*8+7
    {
        const float* ksrc = src + Dd;
        const int par = (r & 1) * 4;
        uint32_t* kd = (uint32_t*)(krh + ((size_t)(bh * 32 + t)) * 4096) + r * 32;
        #pragma unroll
        for (int lw = 0; lw < 8; lw++) {
            const int wdx = c16 * 8 + lw;
            const int g = wdx >> 4, wg = wdx & 15;
            kd[(((g * 4 + (wg & 3)) ^ par)) * 4 + (wg >> 2)] =
                pack_f16x2(ksrc[2 * lw], ksrc[2 * lw + 1]);
        }
    }

    // V tile (fp16, transposed: row=dh, col=key, row stride 72 halves)
    {
        const float* vsrc = src + 2 * Dd;
        uint16_t* vtile = vth + ((size_t)(bh * 32 + t)) * (64 * 72);
        #pragma unroll
        for (int i = 0; i < 16; i++) {
            const int row = c16 * 16 + i;
            __half hv = __float2half_rn(vsrc[i]);
            vtile[(size_t)row * 72 + r] = *(const uint16_t*)&hv;
        }
    }
}

// ---------------------------------------------------------------------------
// GEMM v8 (fp16 m16n8k16, fp32 acc): C[M,N] = A @ B^T + bias.
// A/B pre-tiled fp16 (16KB chunks = K-64, swizzled). 3-buffer bulk-copy
// pipeline, compile-time stage indices. Warp tile 32x64. K=1024 -> 16 chunks.
// ---------------------------------------------------------------------------
__global__ __launch_bounds__(256, 2) void tgemm_v8(
    const uint4* __restrict__ A, const uint4* __restrict__ B,
    const float* __restrict__ bias, float* __restrict__ C, int N)
{
    extern __shared__ uint4 gsm[];           // 3 buffers x 2048 uint4
    __shared__ uint64_t mbars[3];

    const int tid  = threadIdx.x;
    const int lane = tid & 31;
    const int w    = tid >> 5;
    const int qr   = lane >> 2;
    const int qc   = lane & 3;
    const int wm   = w & 3;
    const int wn   = w >> 2;
    const int nb   = blockIdx.x;
    const int mb   = blockIdx.y;

    uint32_t mb0 = (uint32_t)__cvta_generic_to_shared(mbars);
    if (tid == 0)
        for (int s = 0; s < 3; s++) mbar_init(mb0 + s * 8, 1);
    __syncthreads();

    const uint4* Atile = A + (size_t)mb * 16 * 1024;
    const uint4* Btile = B + (size_t)nb * 16 * 1024;

    uint32_t sdst[3];
    #pragma unroll
    for (int s = 0; s < 3; s++)
        sdst[s] = (uint32_t)__cvta_generic_to_shared(gsm + s * 2048);

    if (tid == 0) {
        #pragma unroll
        for (int s = 0; s < 3; s++) {
            mbar_expect_tx(mb0 + s * 8, 32768);
            bulk_g2s(sdst[s],         Atile + s * 1024, 16384, mb0 + s * 8);
            bulk_g2s(sdst[s] + 16384, Btile + s * 1024, 16384, mb0 + s * 8);
        }
    }

    float acc[2][8][4];
    #pragma unroll
    for (int f = 0; f < 2; f++)
        #pragma unroll
        for (int nt = 0; nt < 8; nt++)
            #pragma unroll
            for (int i = 0; i < 4; i++) acc[f][nt][i] = 0.f;

    const int par = (qr & 1) * 4;
    const int cx0 = qc ^ par;
    const int cx1 = (4 + qc) ^ par;

    auto do_chunk = [&](const uint4* __restrict__ buf) {
        const uint4* Ap = buf;
        const uint4* Bp = buf + 1024;
        uint4 Ag0[2][2], Ag1[2][2];          // [f][group][row01]
        #pragma unroll
        for (int f = 0; f < 2; f++) {
            const uint4* r0p = Ap + (wm * 32 + f * 16 + qr) * 8;
            const uint4* r1p = Ap + (wm * 32 + f * 16 + 8 + qr) * 8;
            Ag0[f][0] = r0p[cx0]; Ag0[f][1] = r0p[cx1];
            Ag1[f][0] = r1p[cx0]; Ag1[f][1] = r1p[cx1];
        }
        #pragma unroll
        for (int nt = 0; nt < 8; nt++) {
            const uint4* bp = Bp + (wn * 64 + nt * 8 + qr) * 8;
            uint4 Bg0 = bp[cx0];
            uint4 Bg1 = bp[cx1];
            #pragma unroll
            for (int f = 0; f < 2; f++) {
                mma_f16(acc[f][nt], Ag0[f][0].x, Ag1[f][0].x,
                        Ag0[f][0].y, Ag1[f][0].y, Bg0.x, Bg0.y);
                mma_f16(acc[f][nt], Ag0[f][0].z, Ag1[f][0].z,
                        Ag0[f][0].w, Ag1[f][0].w, Bg0.z, Bg0.w);
                mma_f16(acc[f][nt], Ag0[f][1].x, Ag1[f][1].x,
                        Ag0[f][1].y, Ag1[f][1].y, Bg1.x, Bg1.y);
                mma_f16(acc[f][nt], Ag0[f][1].z, Ag1[f][1].z,
                        Ag0[f][1].w, Ag1[f][1].w, Bg1.z, Bg1.w);
            }
        }
    };

    const uint4* An = Atile + 3 * 1024;
    const uint4* Bn = Btile + 3 * 1024;

    #pragma unroll 1
    for (int g = 0; g < 6; g++) {
        #pragma unroll
        for (int s = 0; s < 3; s++) {
            const int ch = g * 3 + s;
            if (ch >= 16) break;
            mbar_wait(mb0 + s * 8, g & 1);
            do_chunk(gsm + s * 2048);
            __syncthreads();
            if (tid == 0 && ch + 3 < 16) {
                mbar_expect_tx(mb0 + s * 8, 32768);
                bulk_g2s(sdst[s],         An, 16384, mb0 + s * 8);
                bulk_g2s(sdst[s] + 16384, Bn, 16384, mb0 + s * 8);
            }
            An += 1024; Bn += 1024;
        }
    }

    // epilogue
    #pragma unroll
    for (int f = 0; f < 2; f++) {
        const int r = mb * 128 + wm * 32 + f * 16 + qr;
        float* Crow0 = C + (size_t)r * N + nb * 128 + wn * 64;
        float* Crow1 = C + (size_t)(r + 8) * N + nb * 128 + wn * 64;
        #pragma unroll
        for (int nt = 0; nt < 8; nt++) {
            const int c = nt * 8 + qc * 2;
            float2 bv = *(const float2*)&bias[nb * 128 + wn * 64 + c];
            *(float2*)&Crow0[c] = make_float2(acc[f][nt][0] + bv.x,
                                              acc[f][nt][1] + bv.y);
            *(float2*)&Crow1[c] = make_float2(acc[f][nt][2] + bv.x,
                                              acc[f][nt][3] + bv.y);
        }
    }
}

// ---------------------------------------------------------------------------
// Flash attention v5: fp16 QK^T + fp16 PV, fp32 softmax state.
// K fp16 tiles (8KB) + V fp16 tiles (9216B) staged by cp.async.bulk,
// 2-stage pipeline (stage 17408B -> 34816B dynamic smem).
// Epilogue writes fp16 tiled layout for tgemm_v8.
// ---------------------------------------------------------------------------
__global__ __launch_bounds__(256) void flash_attn_v5(
    const float* __restrict__ qkv, const uint16_t* __restrict__ krh,
    const uint16_t* __restrict__ vth, uint16_t* __restrict__ attnrh)
{
    extern __shared__ char dsma[];
    __shared__ uint64_t ambars[2];
    constexpr int STAGE_B = 8192 + 9216;     // 17408
    constexpr float QSCALE = 0.125f * 1.44269504088896341f;

    const int tid  = threadIdx.x;
    const int lane = tid & 31;
    const int w    = tid >> 5;
    const int qr   = lane >> 2;
    const int qc   = lane & 3;
    const int h    = blockIdx.y;
    const int b    = blockIdx.z;
    const int q0   = blockIdx.x * 128;
    const int row0 = w * 16;
    const int bh   = b * Hh + h;

    uint32_t amb = (uint32_t)__cvta_generic_to_shared(ambars);
    uint32_t sb0 = (uint32_t)__cvta_generic_to_shared(dsma);
    if (tid == 0) { mbar_init(amb, 1); mbar_init(amb + 8, 1); }
    __syncthreads();

    const uint16_t* ktiles = krh + (size_t)bh * 32 * 4096;
    const uint16_t* vtiles = vth + (size_t)bh * 32 * (64 * 72);

    if (tid == 0) {
        #pragma unroll
        for (int s = 0; s < 2; s++) {
            mbar_expect_tx(amb + s * 8, STAGE_B);
            bulk_g2s(sb0 + s * STAGE_B,        ktiles + s * 4096,      8192,
                     amb + s * 8);
            bulk_g2s(sb0 + s * STAGE_B + 8192, vtiles + s * (64 * 72), 9216,
                     amb + s * 8);
        }
    }

    // Q into fp16 A-fragments (scaled by dh^-0.5 * log2e)
    uint32_t Qh[4][4];
    {
        const float* qb    = qkv + ((size_t)(b * Nn + q0)) * D3 + h * DHh;
        const float* qrow0 = qb + (size_t)(row0 + qr) * D3;
        const float* qrow1 = qb + (size_t)(row0 + qr + 8) * D3;
        #pragma unroll
        for (int kt = 0; kt < 4; kt++) {
            const int k0 = 16 * kt + 2 * qc;
            Qh[kt][0] = pack_f16x2(qrow0[k0] * QSCALE,     qrow0[k0 + 1] * QSCALE);
            Qh[kt][1] = pack_f16x2(qrow1[k0] * QSCALE,     qrow1[k0 + 1] * QSCALE);
            Qh[kt][2] = pack_f16x2(qrow0[k0 + 8] * QSCALE, qrow0[k0 + 9] * QSCALE);
            Qh[kt][3] = pack_f16x2(qrow1[k0 + 8] * QSCALE, qrow1[k0 + 9] * QSCALE);
        }
    }

    float O[8][4];
    #pragma unroll
    for (int nt = 0; nt < 8; nt++)
        #pragma unroll
        for (int i = 0; i < 4; i++) O[nt][i] = 0.f;
    float mA = -1e30f, mB = -1e30f, lA = 0.f, lB = 0.f;

    const int spar = (qr & 1) * 4;
    const int s0x  = qc ^ spar;
    const int s1x  = (4 + qc) ^ spar;

    for (int t = 0; t < 32; t++) {
        mbar_wait(amb + (t & 1) * 8, (t >> 1) & 1);

        const uint4*    Kp = (const uint4*)(dsma + (t & 1) * STAGE_B);
        const uint32_t* Vp = (const uint32_t*)(dsma + (t & 1) * STAGE_B + 8192);

        // ---- S = Q @ K^T (fp16, fp32 acc) ----
        float S[8][4];
        #pragma unroll
        for (int nt = 0; nt < 8; nt++) {
            const uint4* kp = Kp + (nt * 8 + qr) * 8;
            uint4 g0 = kp[s0x], g1 = kp[s1x];
            S[nt][0] = 0.f; S[nt][1] = 0.f; S[nt][2] = 0.f; S[nt][3] = 0.f;
            mma_f16(S[nt], Qh[0][0], Qh[0][1], Qh[0][2], Qh[0][3], g0.x, g0.y);
            mma_f16(S[nt], Qh[1][0], Qh[1][1], Qh[1][2], Qh[1][3], g0.z, g0.w);
            mma_f16(S[nt], Qh[2][0], Qh[2][1], Qh[2][2], Qh[2][3], g1.x, g1.y);
            mma_f16(S[nt], Qh[3][0], Qh[3][1], Qh[3][2], Qh[3][3], g1.z, g1.w);
        }

        // ---- online softmax (base 2) ----
        float cmA = -1e30f, cmB = -1e30f;
        #pragma unroll
        for (int nt = 0; nt < 8; nt++) {
            cmA = fmaxf(cmA, fmaxf(S[nt][0], S[nt][1]));
            cmB = fmaxf(cmB, fmaxf(S[nt][2], S[nt][3]));
        }
        cmA = fmaxf(cmA, __shfl_xor_sync(0xffffffffu, cmA, 1));
        cmA = fmaxf(cmA, __shfl_xor_sync(0xffffffffu, cmA, 2));
        cmB = fmaxf(cmB, __shfl_xor_sync(0xffffffffu, cmB, 1));
        cmB = fmaxf(cmB, __shfl_xor_sync(0xffffffffu, cmB, 2));

        const float mnA = fmaxf(mA, cmA), mnB = fmaxf(mB, cmB);
        const float corrA = exp2f(mA - mnA), corrB = exp2f(mB - mnB);
        #pragma unroll
        for (int nt = 0; nt < 8; nt++) {
            O[nt][0] *= corrA; O[nt][1] *= corrA;
            O[nt][2] *= corrB; O[nt][3] *= corrB;
        }

        // ---- P = exp2(S-mn) -> fp16 A-fragments; O += P @ V ----
        float psA = 0.f, psB = 0.f;
        #pragma unroll
        for (int kt = 0; kt < 4; kt++) {
            float q00 = exp2f(S[2*kt][0]   - mnA);
            float q01 = exp2f(S[2*kt][1]   - mnA);
            float q10 = exp2f(S[2*kt][2]   - mnB);
            float q11 = exp2f(S[2*kt][3]   - mnB);
            float r00 = exp2f(S[2*kt+1][0] - mnA);
            float r01 = exp2f(S[2*kt+1][1] - mnA);
            float r10 = exp2f(S[2*kt+1][2] - mnB);
            float r11 = exp2f(S[2*kt+1][3] - mnB);
            psA += q00 + q01 + r00 + r01;
            psB += q10 + q11 + r10 + r11;

            uint32_t a0 = pack_f16x2(q00, q01);
            uint32_t a1 = pack_f16x2(q10, q11);
            uint32_t a2 = pack_f16x2(r00, r01);
            uint32_t a3 = pack_f16x2(r10, r11);

            const uint32_t* vb = Vp + 8 * kt + qc;
            #pragma unroll
            for (int nt = 0; nt < 8; nt++) {
                const uint32_t* vr = vb + (nt * 8 + qr) * 36;
                mma_f16(O[nt], a0, a1, a2, a3, vr[0], vr[4]);
            }
        }
        psA += __shfl_xor_sync(0xffffffffu, psA, 1);
        psA += __shfl_xor_sync(0xffffffffu, psA, 2);
        psB += __shfl_xor_sync(0xffffffffu, psB, 1);
        psB += __shfl_xor_sync(0xffffffffu, psB, 2);
        lA = lA * corrA + psA; mA = mnA;
        lB = lB * corrB + psB; mB = mnB;

        __syncthreads();          // all warps done with stage t&1
        if (tid == 0 && t + 2 < 32) {
            const int s = t & 1;
            mbar_expect_tx(amb + s * 8, STAGE_B);
            bulk_g2s(sb0 + s * STAGE_B,
                     ktiles + (size_t)(t + 2) * 4096, 8192, amb + s * 8);
            bulk_g2s(sb0 + s * STAGE_B + 8192,
                     vtiles + (size_t)(t + 2) * (64 * 72), 9216, amb + s * 8);
        }
    }

    // ---- epilogue: fp16 words into tgemm_v8's tile layout ----
    const float invA = 1.f / lA, invB = 1.f / lB;
    const int bq = b * Nn + q0;
    #pragma unroll
    for (int half = 0; half < 2; half++) {
        const int R  = bq + row0 + qr + half * 8;
        const int rb = R >> 7, r = R & 127;
        const int par = (r & 1) * 4;
        #pragma unroll
        for (int nt = 0; nt < 8; nt++) {
            const int W  = h * 32 + nt * 4 + qc;     // word index in 512-word row
            const int kb = W >> 5;
            const int w32 = W & 31;
            const int g = w32 >> 4, wg = w32 & 15;
            uint32_t val = (half == 0)
                ? pack_f16x2(O[nt][0] * invA, O[nt][1] * invA)
                : pack_f16x2(O[nt][2] * invB, O[nt][3] * invB);
            uint32_t* dst = (uint32_t*)attnrh
                + ((size_t)(rb * 16 + kb) * 128 + r) * 32
                + ((g * 4 + (wg & 3)) ^ par) * 4 + (wg >> 2);
            *dst = val;
        }
    }
}

// ---------------------------------------------------------------------------
// Host launcher
// ---------------------------------------------------------------------------
extern "C" void kernel_launch(void* const* d_in, const int* in_sizes, int n_in,
                              void* d_out, int out_size)
{
    const float* x     = (const float*)d_in[0];
    const float* W_w   = (const float*)d_in[1];
    const float* W_b   = (const float*)d_in[2];
    const float* out_w = (const float*)d_in[3];
    const float* out_b = (const float*)d_in[4];

    float* qkv;
    uint16_t *xr, *wwr, *owr, *attnrh, *krh, *vth;
    cudaGetSymbolAddress((void**)&qkv,    g_qkv);
    cudaGetSymbolAddress((void**)&xr,     g_xr);
    cudaGetSymbolAddress((void**)&wwr,    g_wwr);
    cudaGetSymbolAddress((void**)&owr,    g_owr);
    cudaGetSymbolAddress((void**)&attnrh, g_attnrh);
    cudaGetSymbolAddress((void**)&krh,    g_krh);
    cudaGetSymbolAddress((void**)&vth,    g_vth);

    const int M = Bb * Nn;                        // 4096
    const int GEMM_SMEM = 3 * 2048 * 16;          // 96 KB
    const int ATTN_SMEM = 2 * 17408;              // 34816 B

    cudaFuncSetAttribute(tgemm_v8,
                         cudaFuncAttributeMaxDynamicSharedMemorySize, GEMM_SMEM);
    cudaFuncSetAttribute(flash_attn_v5,
                         cudaFuncAttributeMaxDynamicSharedMemorySize, ATTN_SMEM);

    // pre-pass: fp16 tile/repack/swizzle of GEMM operands
    repack_tiles_f16<<<M * 16 / 256,  256>>>(x,     xr,  M);
    repack_tiles_f16<<<D3 * 16 / 256, 256>>>(W_w,   wwr, D3);
    repack_tiles_f16<<<Dd * 16 / 256, 256>>>(out_w, owr, Dd);

    // qkv = x @ W_w^T + W_b
    tgemm_v8<<<dim3(D3 / 128, M / 128), 256, GEMM_SMEM>>>(
        (const uint4*)xr, (const uint4*)wwr, W_b, qkv, D3);

    // prep K/V tile layouts
    prep_kv<<<(Bb * Hh * 4 * Nn) / 256, 256>>>(qkv, krh, vth);

    // attention -> attnrh (fp16 tiled layout)
    flash_attn_v5<<<dim3(Nn / 128, Hh, Bb), 256, ATTN_SMEM>>>(qkv, krh, vth,
                                                              attnrh);

    // out = attn @ out_w^T + out_b
    tgemm_v8<<<dim3(Dd / 128, M / 128), 256, GEMM_SMEM>>>(
        (const uint4*)attnrh, (const uint4*)owr, out_b, (float*)d_out, Dd);
}

// round 17
// speedup vs baseline: 2.2897x; 1.0987x over previous
#include <cuda_runtime.h>
#include <cuda_fp16.h>
#include <math.h>
#include <stdint.h>

// Problem constants
constexpr int Bb  = 2;
constexpr int Nn  = 2048;
constexpr int Dd  = 1024;
constexpr int Hh  = 16;
constexpr int DHh = 64;
constexpr int D3  = 3 * Dd;   // 3072

// Scratch (allocation-free rule: __device__ globals)
__device__ uint16_t g_xr[Bb * Nn * Dd];        // x fp16 tiles
__device__ uint16_t g_wwr[D3 * Dd];            // W_w fp16 tiles
__device__ uint16_t g_owr[Dd * Dd];            // out_w fp16 tiles
__device__ uint16_t g_attnrh[Bb * Nn * Dd];    // attn fp16 tiles
__device__ uint16_t g_q16[Bb * Nn * Dd];       // Q fp16, pre-scaled, row-major
__device__ uint16_t g_krh[Bb * Hh * Nn * DHh];       // K fp16 tiles [bh][t][64][64]
__device__ uint16_t g_vth[Bb * Hh * 32 * 64 * 72];   // V fp16 tiles [bh][t][64dh][72key]

constexpr float QSCALE = 0.125f * 1.44269504088896341f;  // dh^-0.5 * log2e

// ---------------------------------------------------------------------------
// helpers
// ---------------------------------------------------------------------------
__device__ __forceinline__ uint32_t pack_f16x2(float lo, float hi) {
    uint32_t r;
    asm("cvt.rn.f16x2.f32 %0, %1, %2;" : "=r"(r) : "f"(hi), "f"(lo));
    return r;
}

__device__ __forceinline__ void mma_f16(
    float* c, uint32_t a0, uint32_t a1, uint32_t a2, uint32_t a3,
    uint32_t b0, uint32_t b1)
{
    asm volatile(
        "mma.sync.aligned.m16n8k16.row.col.f32.f16.f16.f32 "
        "{%0,%1,%2,%3}, {%4,%5,%6,%7}, {%8,%9}, {%0,%1,%2,%3};\n"
        : "+f"(c[0]), "+f"(c[1]), "+f"(c[2]), "+f"(c[3])
        : "r"(a0), "r"(a1), "r"(a2), "r"(a3), "r"(b0), "r"(b1));
}

__device__ __forceinline__ void mbar_init(uint32_t mbar, uint32_t cnt) {
    asm volatile("mbarrier.init.shared.b64 [%0], %1;" :: "r"(mbar), "r"(cnt)
                 : "memory");
}
__device__ __forceinline__ void mbar_expect_tx(uint32_t mbar, uint32_t bytes) {
    asm volatile("mbarrier.arrive.expect_tx.shared.b64 _, [%0], %1;"
                 :: "r"(mbar), "r"(bytes) : "memory");
}
__device__ __forceinline__ void mbar_wait(uint32_t mbar, uint32_t parity) {
    asm volatile(
        "{\n\t.reg .pred P;\n\t"
        "W%=:\n\t"
        "mbarrier.try_wait.parity.shared.b64 P, [%0], %1;\n\t"
        "@!P bra W%=;\n\t}"
        :: "r"(mbar), "r"(parity) : "memory");
}
__device__ __forceinline__ void bulk_g2s(uint32_t dst, const void* src,
                                         uint32_t bytes, uint32_t mbar) {
    asm volatile(
        "cp.async.bulk.shared::cta.global.mbarrier::complete_tx::bytes "
        "[%0], [%1], %2, [%3];"
        :: "r"(dst), "l"(src), "r"(bytes), "r"(mbar) : "memory");
}

// ---------------------------------------------------------------------------
// repack_tiles_f16 (unchanged from R15)
// ---------------------------------------------------------------------------
__global__ void repack_tiles_f16(const float* __restrict__ in,
                                 uint16_t* __restrict__ out, int nrows)
{
    int idx = blockIdx.x * blockDim.x + threadIdx.x;
    if (idx >= nrows * 16) return;
    const int R  = idx >> 4;
    const int kb = idx & 15;
    const int rb = R >> 7, r = R & 127;
    const int par = (r & 1) * 4;

    const float4* ip = (const float4*)(in + (size_t)R * 1024 + kb * 64);
    uint32_t wb[32];
    #pragma unroll
    for (int j = 0; j < 16; j++) {
        float4 v = ip[j];
        wb[2 * j]     = pack_f16x2(v.x, v.y);
        wb[2 * j + 1] = pack_f16x2(v.z, v.w);
    }
    uint4* op = (uint4*)out + ((size_t)(rb * 16 + kb) * 128 + r) * 8;
    #pragma unroll
    for (int g = 0; g < 2; g++)
        #pragma unroll
        for (int t = 0; t < 4; t++)
            op[(g * 4 + t) ^ par] = make_uint4(wb[g * 16 + t],
                                               wb[g * 16 + 4 + t],
                                               wb[g * 16 + 8 + t],
                                               wb[g * 16 + 12 + t]);
}

// ---------------------------------------------------------------------------
// GEMM mainloop core (shared by both GEMM kernels): fp16 m16n8k16, fp32 acc,
// 3-buffer bulk-copy pipeline.
// ---------------------------------------------------------------------------
struct GemmCtx {
    float acc[2][8][4];
};

__device__ __forceinline__ void gemm_mainloop(
    const uint4* __restrict__ Atile, const uint4* __restrict__ Btile,
    uint4* gsm, uint32_t mb0, GemmCtx& ctx,
    int tid, int qr, int qc, int wm, int wn)
{
    uint32_t sdst[3];
    #pragma unroll
    for (int s = 0; s < 3; s++)
        sdst[s] = (uint32_t)__cvta_generic_to_shared(gsm + s * 2048);

    if (tid == 0) {
        #pragma unroll
        for (int s = 0; s < 3; s++) {
            mbar_expect_tx(mb0 + s * 8, 32768);
            bulk_g2s(sdst[s],         Atile + s * 1024, 16384, mb0 + s * 8);
            bulk_g2s(sdst[s] + 16384, Btile + s * 1024, 16384, mb0 + s * 8);
        }
    }

    #pragma unroll
    for (int f = 0; f < 2; f++)
        #pragma unroll
        for (int nt = 0; nt < 8; nt++)
            #pragma unroll
            for (int i = 0; i < 4; i++) ctx.acc[f][nt][i] = 0.f;

    const int par = (qr & 1) * 4;
    const int cx0 = qc ^ par;
    const int cx1 = (4 + qc) ^ par;

    const uint4* An = Atile + 3 * 1024;
    const uint4* Bn = Btile + 3 * 1024;

    #pragma unroll 1
    for (int g = 0; g < 6; g++) {
        #pragma unroll
        for (int s = 0; s < 3; s++) {
            const int ch = g * 3 + s;
            if (ch >= 16) break;
            mbar_wait(mb0 + s * 8, g & 1);

            const uint4* buf = gsm + s * 2048;
            const uint4* Ap = buf;
            const uint4* Bp = buf + 1024;
            uint4 Ag0[2][2], Ag1[2][2];
            #pragma unroll
            for (int f = 0; f < 2; f++) {
                const uint4* r0p = Ap + (wm * 32 + f * 16 + qr) * 8;
                const uint4* r1p = Ap + (wm * 32 + f * 16 + 8 + qr) * 8;
                Ag0[f][0] = r0p[cx0]; Ag0[f][1] = r0p[cx1];
                Ag1[f][0] = r1p[cx0]; Ag1[f][1] = r1p[cx1];
            }
            #pragma unroll
            for (int nt = 0; nt < 8; nt++) {
                const uint4* bp = Bp + (wn * 64 + nt * 8 + qr) * 8;
                uint4 Bg0 = bp[cx0];
                uint4 Bg1 = bp[cx1];
                #pragma unroll
                for (int f = 0; f < 2; f++) {
                    mma_f16(ctx.acc[f][nt], Ag0[f][0].x, Ag1[f][0].x,
                            Ag0[f][0].y, Ag1[f][0].y, Bg0.x, Bg0.y);
                    mma_f16(ctx.acc[f][nt], Ag0[f][0].z, Ag1[f][0].z,
                            Ag0[f][0].w, Ag1[f][0].w, Bg0.z, Bg0.w);
                    mma_f16(ctx.acc[f][nt], Ag0[f][1].x, Ag1[f][1].x,
                            Ag0[f][1].y, Ag1[f][1].y, Bg1.x, Bg1.y);
                    mma_f16(ctx.acc[f][nt], Ag0[f][1].z, Ag1[f][1].z,
                            Ag0[f][1].w, Ag1[f][1].w, Bg1.z, Bg1.w);
                }
            }

            __syncthreads();
            if (tid == 0 && ch + 3 < 16) {
                mbar_expect_tx(mb0 + s * 8, 32768);
                bulk_g2s(sdst[s],         An, 16384, mb0 + s * 8);
                bulk_g2s(sdst[s] + 16384, Bn, 16384, mb0 + s * 8);
            }
            An += 1024; Bn += 1024;
        }
    }
}

// ---------------------------------------------------------------------------
// tgemm_qkv: QKV projection with FUSED layout epilogue.
// nb<8: Q -> g_q16 (fp16, pre-scaled by QSCALE, row-major [token][512w])
// 8<=nb<16: K -> g_krh tile layout (swizzled, rows=key)
// nb>=16: V -> g_vth transposed tiles [dh][key stride 72]
// ---------------------------------------------------------------------------
__global__ __launch_bounds__(256, 2) void tgemm_qkv(
    const uint4* __restrict__ A, const uint4* __restrict__ B,
    const float* __restrict__ bias,
    uint16_t* __restrict__ q16, uint16_t* __restrict__ krh,
    uint16_t* __restrict__ vth)
{
    extern __shared__ uint4 gsm[];
    __shared__ uint64_t mbars[3];

    const int tid  = threadIdx.x;
    const int lane = tid & 31;
    const int w    = tid >> 5;
    const int qr   = lane >> 2;
    const int qc   = lane & 3;
    const int wm   = w & 3;
    const int wn   = w >> 2;
    const int nb   = blockIdx.x;
    const int mb   = blockIdx.y;

    uint32_t mb0 = (uint32_t)__cvta_generic_to_shared(mbars);
    if (tid == 0)
        for (int s = 0; s < 3; s++) mbar_init(mb0 + s * 8, 1);
    __syncthreads();

    GemmCtx ctx;
    gemm_mainloop(A + (size_t)mb * 16 * 1024, B + (size_t)nb * 16 * 1024,
                  gsm, mb0, ctx, tid, qr, qc, wm, wn);

    // ---- fused epilogue ----
    const int colbase = nb * 128 + wn * 64;
    #pragma unroll
    for (int f = 0; f < 2; f++) {
        const int R0 = mb * 128 + wm * 32 + f * 16 + qr;   // token rows R0, R0+8
        #pragma unroll
        for (int half = 0; half < 2; half++) {
            const int R = R0 + half * 8;
            const int n = R & (Nn - 1);
            const int b = R >> 11;
            #pragma unroll
            for (int nt = 0; nt < 8; nt++) {
                const int col = colbase + nt * 8 + qc * 2;
                float2 bv = *(const float2*)&bias[col];
                float v0 = ctx.acc[f][nt][half * 2]     + bv.x;
                float v1 = ctx.acc[f][nt][half * 2 + 1] + bv.y;

                if (nb < 8) {
                    // Q: pre-scale, fp16 word row-major
                    uint32_t word = pack_f16x2(v0 * QSCALE, v1 * QSCALE);
                    ((uint32_t*)q16)[(size_t)R * 512 + (col >> 1)] = word;
                } else if (nb < 16) {
                    // K: swizzled tile word
                    const int kf = col - Dd;
                    const int h  = kf >> 6, dh = kf & 63;
                    const int bh = b * Hh + h;
                    const int t  = n >> 6, r = n & 63;
                    const int pr = (r & 1) * 4;
                    const int wdx = dh >> 1;
                    const int g = wdx >> 4, wg = wdx & 15;
                    uint32_t* kd = (uint32_t*)(krh
                        + ((size_t)(bh * 32 + t)) * 4096) + r * 32;
                    kd[((g * 4 + (wg & 3)) ^ pr) * 4 + (wg >> 2)] =
                        pack_f16x2(v0, v1);
                } else {
                    // V: transposed halves
                    const int vf = col - 2 * Dd;
                    const int h  = vf >> 6, dh = vf & 63;
                    const int bh = b * Hh + h;
                    const int t  = n >> 6, r = n & 63;
                    uint16_t* vtile = vth + ((size_t)(bh * 32 + t)) * (64 * 72);
                    __half h0 = __float2half_rn(v0);
                    __half h1 = __float2half_rn(v1);
                    vtile[(size_t)dh * 72 + r]       = *(const uint16_t*)&h0;
                    vtile[(size_t)(dh + 1) * 72 + r] = *(const uint16_t*)&h1;
                }
            }
        }
    }
}

// ---------------------------------------------------------------------------
// tgemm_v8 (unchanged): plain fp16 GEMM with fp32 output + bias.
// ---------------------------------------------------------------------------
__global__ __launch_bounds__(256, 2) void tgemm_v8(
    const uint4* __restrict__ A, const uint4* __restrict__ B,
    const float* __restrict__ bias, float* __restrict__ C, int N)
{
    extern __shared__ uint4 gsm[];
    __shared__ uint64_t mbars[3];

    const int tid  = threadIdx.x;
    const int lane = tid & 31;
    const int w    = tid >> 5;
    const int qr   = lane >> 2;
    const int qc   = lane & 3;
    const int wm   = w & 3;
    const int wn   = w >> 2;
    const int nb   = blockIdx.x;
    const int mb   = blockIdx.y;

    uint32_t mb0 = (uint32_t)__cvta_generic_to_shared(mbars);
    if (tid == 0)
        for (int s = 0; s < 3; s++) mbar_init(mb0 + s * 8, 1);
    __syncthreads();

    GemmCtx ctx;
    gemm_mainloop(A + (size_t)mb * 16 * 1024, B + (size_t)nb * 16 * 1024,
                  gsm, mb0, ctx, tid, qr, qc, wm, wn);

    #pragma unroll
    for (int f = 0; f < 2; f++) {
        const int r = mb * 128 + wm * 32 + f * 16 + qr;
        float* Crow0 = C + (size_t)r * N + nb * 128 + wn * 64;
        float* Crow1 = C + (size_t)(r + 8) * N + nb * 128 + wn * 64;
        #pragma unroll
        for (int nt = 0; nt < 8; nt++) {
            const int c = nt * 8 + qc * 2;
            float2 bv = *(const float2*)&bias[nb * 128 + wn * 64 + c];
            *(float2*)&Crow0[c] = make_float2(ctx.acc[f][nt][0] + bv.x,
                                              ctx.acc[f][nt][1] + bv.y);
            *(float2*)&Crow1[c] = make_float2(ctx.acc[f][nt][2] + bv.x,
                                              ctx.acc[f][nt][3] + bv.y);
        }
    }
}

// ---------------------------------------------------------------------------
// Flash attention v6: fp16 QK^T + fp16 PV; Q loaded pre-scaled fp16.
// ---------------------------------------------------------------------------
__global__ __launch_bounds__(256) void flash_attn_v6(
    const uint16_t* __restrict__ q16, const uint16_t* __restrict__ krh,
    const uint16_t* __restrict__ vth, uint16_t* __restrict__ attnrh)
{
    extern __shared__ char dsma[];
    __shared__ uint64_t ambars[2];
    constexpr int STAGE_B = 8192 + 9216;     // 17408

    const int tid  = threadIdx.x;
    const int lane = tid & 31;
    const int w    = tid >> 5;
    const int qr   = lane >> 2;
    const int qc   = lane & 3;
    const int h    = blockIdx.y;
    const int b    = blockIdx.z;
    const int q0   = blockIdx.x * 128;
    const int row0 = w * 16;
    const int bh   = b * Hh + h;

    uint32_t amb = (uint32_t)__cvta_generic_to_shared(ambars);
    uint32_t sb0 = (uint32_t)__cvta_generic_to_shared(dsma);
    if (tid == 0) { mbar_init(amb, 1); mbar_init(amb + 8, 1); }
    __syncthreads();

    const uint16_t* ktiles = krh + (size_t)bh * 32 * 4096;
    const uint16_t* vtiles = vth + (size_t)bh * 32 * (64 * 72);

    if (tid == 0) {
        #pragma unroll
        for (int s = 0; s < 2; s++) {
            mbar_expect_tx(amb + s * 8, STAGE_B);
            bulk_g2s(sb0 + s * STAGE_B,        ktiles + s * 4096,      8192,
                     amb + s * 8);
            bulk_g2s(sb0 + s * STAGE_B + 8192, vtiles + s * (64 * 72), 9216,
                     amb + s * 8);
        }
    }

    // Q fragments: pre-scaled fp16 words, direct loads
    uint32_t Qh[4][4];
    {
        const uint32_t* qr0 = (const uint32_t*)q16
            + (size_t)(b * Nn + q0 + row0 + qr) * 512 + h * 32;
        const uint32_t* qr1 = qr0 + (size_t)8 * 512;
        #pragma unroll
        for (int kt = 0; kt < 4; kt++) {
            Qh[kt][0] = qr0[8 * kt + qc];
            Qh[kt][1] = qr1[8 * kt + qc];
            Qh[kt][2] = qr0[8 * kt + qc + 4];
            Qh[kt][3] = qr1[8 * kt + qc + 4];
        }
    }

    float O[8][4];
    #pragma unroll
    for (int nt = 0; nt < 8; nt++)
        #pragma unroll
        for (int i = 0; i < 4; i++) O[nt][i] = 0.f;
    float mA = -1e30f, mB = -1e30f, lA = 0.f, lB = 0.f;

    const int spar = (qr & 1) * 4;
    const int s0x  = qc ^ spar;
    const int s1x  = (4 + qc) ^ spar;

    for (int t = 0; t < 32; t++) {
        mbar_wait(amb + (t & 1) * 8, (t >> 1) & 1);

        const uint4*    Kp = (const uint4*)(dsma + (t & 1) * STAGE_B);
        const uint32_t* Vp = (const uint32_t*)(dsma + (t & 1) * STAGE_B + 8192);

        // ---- S = Q @ K^T ----
        float S[8][4];
        #pragma unroll
        for (int nt = 0; nt < 8; nt++) {
            const uint4* kp = Kp + (nt * 8 + qr) * 8;
            uint4 g0 = kp[s0x], g1 = kp[s1x];
            S[nt][0] = 0.f; S[nt][1] = 0.f; S[nt][2] = 0.f; S[nt][3] = 0.f;
            mma_f16(S[nt], Qh[0][0], Qh[0][1], Qh[0][2], Qh[0][3], g0.x, g0.y);
            mma_f16(S[nt], Qh[1][0], Qh[1][1], Qh[1][2], Qh[1][3], g0.z, g0.w);
            mma_f16(S[nt], Qh[2][0], Qh[2][1], Qh[2][2], Qh[2][3], g1.x, g1.y);
            mma_f16(S[nt], Qh[3][0], Qh[3][1], Qh[3][2], Qh[3][3], g1.z, g1.w);
        }

        // ---- online softmax (base 2) ----
        float cmA = -1e30f, cmB = -1e30f;
        #pragma unroll
        for (int nt = 0; nt < 8; nt++) {
            cmA = fmaxf(cmA, fmaxf(S[nt][0], S[nt][1]));
            cmB = fmaxf(cmB, fmaxf(S[nt][2], S[nt][3]));
        }
        cmA = fmaxf(cmA, __shfl_xor_sync(0xffffffffu, cmA, 1));
        cmA = fmaxf(cmA, __shfl_xor_sync(0xffffffffu, cmA, 2));
        cmB = fmaxf(cmB, __shfl_xor_sync(0xffffffffu, cmB, 1));
        cmB = fmaxf(cmB, __shfl_xor_sync(0xffffffffu, cmB, 2));

        const float mnA = fmaxf(mA, cmA), mnB = fmaxf(mB, cmB);
        const float corrA = exp2f(mA - mnA), corrB = exp2f(mB - mnB);
        #pragma unroll
        for (int nt = 0; nt < 8; nt++) {
            O[nt][0] *= corrA; O[nt][1] *= corrA;
            O[nt][2] *= corrB; O[nt][3] *= corrB;
        }

        // ---- P = exp2(S-mn) -> fp16 A-fragments; O += P @ V ----
        float psA = 0.f, psB = 0.f;
        #pragma unroll
        for (int kt = 0; kt < 4; kt++) {
            float q00 = exp2f(S[2*kt][0]   - mnA);
            float q01 = exp2f(S[2*kt][1]   - mnA);
            float q10 = exp2f(S[2*kt][2]   - mnB);
            float q11 = exp2f(S[2*kt][3]   - mnB);
            float r00 = exp2f(S[2*kt+1][0] - mnA);
            float r01 = exp2f(S[2*kt+1][1] - mnA);
            float r10 = exp2f(S[2*kt+1][2] - mnB);
            float r11 = exp2f(S[2*kt+1][3] - mnB);
            psA += q00 + q01 + r00 + r01;
            psB += q10 + q11 + r10 + r11;

            uint32_t a0 = pack_f16x2(q00, q01);
            uint32_t a1 = pack_f16x2(q10, q11);
            uint32_t a2 = pack_f16x2(r00, r01);
            uint32_t a3 = pack_f16x2(r10, r11);

            const uint32_t* vb = Vp + 8 * kt + qc;
            #pragma unroll
            for (int nt = 0; nt < 8; nt++) {
                const uint32_t* vr = vb + (nt * 8 + qr) * 36;
                mma_f16(O[nt], a0, a1, a2, a3, vr[0], vr[4]);
            }
        }
        psA += __shfl_xor_sync(0xffffffffu, psA, 1);
        psA += __shfl_xor_sync(0xffffffffu, psA, 2);
        psB += __shfl_xor_sync(0xffffffffu, psB, 1);
        psB += __shfl_xor_sync(0xffffffffu, psB, 2);
        lA = lA * corrA + psA; mA = mnA;
        lB = lB * corrB + psB; mB = mnB;

        __syncthreads();
        if (tid == 0 && t + 2 < 32) {
            const int s = t & 1;
            mbar_expect_tx(amb + s * 8, STAGE_B);
            bulk_g2s(sb0 + s * STAGE_B,
                     ktiles + (size_t)(t + 2) * 4096, 8192, amb + s * 8);
            bulk_g2s(sb0 + s * STAGE_B + 8192,
                     vtiles + (size_t)(t + 2) * (64 * 72), 9216, amb + s * 8);
        }
    }

    // ---- epilogue: fp16 words into tgemm_v8's tile layout ----
    const float invA = 1.f / lA, invB = 1.f / lB;
    const int bq = b * Nn + q0;
    #pragma unroll
    for (int half = 0; half < 2; half++) {
        const int R  = bq + row0 + qr + half * 8;
        const int rb = R >> 7, r = R & 127;
        const int par = (r & 1) * 4;
        #pragma unroll
        for (int nt = 0; nt < 8; nt++) {
            const int W  = h * 32 + nt * 4 + qc;
            const int kb = W >> 5;
            const int w32 = W & 31;
            const int g = w32 >> 4, wg = w32 & 15;
            uint32_t val = (half == 0)
                ? pack_f16x2(O[nt][0] * invA, O[nt][1] * invA)
                : pack_f16x2(O[nt][2] * invB, O[nt][3] * invB);
            uint32_t* dst = (uint32_t*)attnrh
                + ((size_t)(rb * 16 + kb) * 128 + r) * 32
                + ((g * 4 + (wg & 3)) ^ par) * 4 + (wg >> 2);
            *dst = val;
        }
    }
}

// ---------------------------------------------------------------------------
// Host launcher
// ---------------------------------------------------------------------------
extern "C" void kernel_launch(void* const* d_in, const int* in_sizes, int n_in,
                              void* d_out, int out_size)
{
    const float* x     = (const float*)d_in[0];
    const float* W_w   = (const float*)d_in[1];
    const float* W_b   = (const float*)d_in[2];
    const float* out_w = (const float*)d_in[3];
    const float* out_b = (const float*)d_in[4];

    uint16_t *xr, *wwr, *owr, *attnrh, *q16, *krh, *vth;
    cudaGetSymbolAddress((void**)&xr,     g_xr);
    cudaGetSymbolAddress((void**)&wwr,    g_wwr);
    cudaGetSymbolAddress((void**)&owr,    g_owr);
    cudaGetSymbolAddress((void**)&attnrh, g_attnrh);
    cudaGetSymbolAddress((void**)&q16,    g_q16);
    cudaGetSymbolAddress((void**)&krh,    g_krh);
    cudaGetSymbolAddress((void**)&vth,    g_vth);

    const int M = Bb * Nn;                        // 4096
    const int GEMM_SMEM = 3 * 2048 * 16;          // 96 KB
    const int ATTN_SMEM = 2 * 17408;              // 34816 B

    cudaFuncSetAttribute(tgemm_qkv,
                         cudaFuncAttributeMaxDynamicSharedMemorySize, GEMM_SMEM);
    cudaFuncSetAttribute(tgemm_v8,
                         cudaFuncAttributeMaxDynamicSharedMemorySize, GEMM_SMEM);
    cudaFuncSetAttribute(flash_attn_v6,
                         cudaFuncAttributeMaxDynamicSharedMemorySize, ATTN_SMEM);

    // pre-pass: fp16 tile/repack/swizzle of GEMM operands
    repack_tiles_f16<<<M * 16 / 256,  256>>>(x,     xr,  M);
    repack_tiles_f16<<<D3 * 16 / 256, 256>>>(W_w,   wwr, D3);
    repack_tiles_f16<<<Dd * 16 / 256, 256>>>(out_w, owr, Dd);

    // QKV projection with fused Q/K/V layout epilogue
    tgemm_qkv<<<dim3(D3 / 128, M / 128), 256, GEMM_SMEM>>>(
        (const uint4*)xr, (const uint4*)wwr, W_b, q16, krh, vth);

    // attention -> attnrh (fp16 tiled layout)
    flash_attn_v6<<<dim3(Nn / 128, Hh, Bb), 256, ATTN_SMEM>>>(q16, krh, vth,
                                                              attnrh);

    // out = attn @ out_w^T + out_b
    tgemm_v8<<<dim3(Dd / 128, M / 128), 256, GEMM_SMEM>>>(
        (const uint4*)attnrh, (const uint4*)owr, out_b, (float*)d_out, Dd);
}